// round 10
// baseline (speedup 1.0000x reference)
#include <cuda_runtime.h>
#include <cuda_bf16.h>
#include <math.h>

#define NB 256
#define BATCHN 128
#define NSTEPS 100
#define MAXEV 5
#define HID 64
#define NTH 512
#define NWARP (NTH/32)
#define NSEGB 385
#define NSEGN 96
#define MB 1.0f
#define MN 0.25f

#define BAR_SYNC(id,cnt)   asm volatile("bar.sync %0, %1;"   :: "r"(id), "r"(cnt) : "memory")

__device__ __forceinline__ float silu_f(float x) {
    return x / (1.0f + expf(-x));
}

__device__ __forceinline__ void fold_ball_key(unsigned long long& key, int p, float d2, float two_r) {
    float gap = sqrtf(d2) - two_r;
    unsigned gu = __float_as_uint(gap);
    gu = (gu & 0x80000000u) ? ~gu : (gu | 0x80000000u);
    unsigned long long k = ((unsigned long long)gu << 32) | (unsigned)p;
    if (k < key) key = k;
}

__global__ __launch_bounds__(NTH, 1)
void hybrid_rollout(const float* __restrict__ g_state,
                    const float* __restrict__ g_radii,
                    const float* __restrict__ g_W1,
                    const float* __restrict__ g_b1,
                    const float* __restrict__ g_W2,
                    const float* __restrict__ g_b2,
                    const float* __restrict__ g_W3,
                    const float* __restrict__ g_b3,
                    float* __restrict__ g_out)
{
    __shared__ float4 own[NB];                 // this block's batch element
    __shared__ float4 bb0[NB];                 // private copy of batch element 0
    __shared__ float2 posA[NB];                // position mirror of bb0
    __shared__ float4 w2q[16*HID];             // w2q[k4*HID+o] = W2[o][4k4..4k4+3]
    __shared__ float w1s[2*HID];
    __shared__ float b1s[HID], b2s[HID], w3s[HID];
    __shared__ float4 h1q[2*16];
    __shared__ float h2buf[2*HID];
    __shared__ unsigned long long redK[NWARP];
    __shared__ float vmaxW[NWARP];
    __shared__ int nBW[NWARP], nNW[NWARP];
    __shared__ int candB[NWARP*NSEGB];         // broad list, per-warp segments, (lo<<8)|hi
    __shared__ int candN[NWARP*NSEGN];         // near list, per-warp segments
    __shared__ int sVmax2i;
    __shared__ float sMotB, sMotN;             // motion bound since broad / near rebuild
    __shared__ int sOvB, sOvN;
    __shared__ float sb3, srr;

    const int tid  = threadIdx.x;
    const int bidx = blockIdx.x;
    const int i0   = tid & (NB-1);
    const int half = tid >> 8;
    const int lane = tid & 31;
    const int warp = tid >> 5;

    // ---- setup ----
    if (tid < NB) {
        float4 v = reinterpret_cast<const float4*>(g_state)[bidx*NB + tid];
        own[tid] = v;
        float4 c = reinterpret_cast<const float4*>(g_state)[tid];
        bb0[tid] = c;
        posA[tid] = make_float2(c.x, c.y);
        reinterpret_cast<float4*>(g_out)[bidx*NB + tid] = v;
    }
    for (int q = tid; q < 16*HID; q += NTH) {
        int o = q & 63, k4 = q >> 6;
        const float* src = g_W2 + o*HID + k4*4;
        w2q[q] = make_float4(src[0], src[1], src[2], src[3]);
    }
    if (tid < 2*HID) w1s[tid] = g_W1[tid];
    if (tid < HID) { b1s[tid] = g_b1[tid]; b2s[tid] = g_b2[tid]; w3s[tid] = g_W3[tid]; }
    if (tid == 0) {
        sb3 = g_b3[0]; srr = g_radii[0];
        sMotB = 1e30f; sMotN = 1e30f; sVmax2i = 0; sOvB = 0; sOvN = 0;
    }
    __syncthreads();

    const float rr    = srr;
    const float two_r = rr + rr;
    const float cut   = two_r + 0.051f;        // exact narrow cutoff
    const float c2    = cut * cut;
    const float cutN  = cut + MN;
    const float c2n   = cutN * cutN;
    const float cutB  = cut + MB;
    const float c2b   = cutB * cutB;
    const float b3v   = sb3;

    for (int s = 0; s < NSTEPS; ++s) {
        const float t_s = (float)s * 0.05f;
        const float t_e = t_s + 0.05f;
        float t_c = t_s;

        for (int ev = 0; ev < MAXEV; ++ev) {
            // ================= P0: detection =================
            const bool bRb = (sOvB != 0) || (sMotB >= (MB - MN));
            const bool nRb = (!bRb) && ((sOvN != 0) || (sMotN >= MN));
            const float4 me = bb0[i0];
            unsigned long long key = ~0ull;

            if (bRb) {
                // full rotated pair scan; rebuild broad + near; keys inline
                float m = me.z*me.z + me.w*me.w;
                #pragma unroll
                for (int off = 16; off > 0; off >>= 1)
                    m = fmaxf(m, __shfl_down_sync(0xFFFFFFFFu, m, off));
                if (lane == 0) vmaxW[warp] = m;

                int cntB = 0, cntN = 0;
                const int bBase = warp * NSEGB, nBase = warp * NSEGN;
                for (int d = 1 + half; d <= 128; d += 2) {
                    if (d == 128 && i0 >= 128) break;      // warp-uniform
                    int j = (i0 + d) & (NB-1);
                    float2 pj = posA[j];
                    float dx = pj.x - me.x, dy = pj.y - me.y;
                    float d2 = dx*dx + dy*dy;
                    bool pb = (d2 <= c2b);
                    unsigned mskb = __ballot_sync(0xFFFFFFFFu, pb);
                    int p = 0;
                    if (pb) {
                        int lo = (i0 < j) ? i0 : j;
                        int hi = (i0 < j) ? j : i0;
                        p = (lo << 8) | hi;
                        int sB = cntB + __popc(mskb & ((1u << lane) - 1u));
                        if (sB < NSEGB) candB[bBase + sB] = p;
                    }
                    cntB += __popc(mskb);
                    bool pn = (d2 <= c2n);
                    unsigned mskn = __ballot_sync(0xFFFFFFFFu, pn);
                    if (pn) {
                        int sN = cntN + __popc(mskn & ((1u << lane) - 1u));
                        if (sN < NSEGN) candN[nBase + sN] = p;
                        if (d2 <= c2) {
                            float4 oj = bb0[j];
                            float dvx = oj.z - me.z, dvy = oj.w - me.w;
                            if (dvx*dx + dvy*dy < 0.0f)
                                fold_ball_key(key, p, d2, two_r);
                        }
                    }
                    cntN += __popc(mskn);
                }
                if (lane == 0) { nBW[warp] = cntB; nNW[warp] = cntN; }
            } else if (nRb) {
                // rebuild near from this warp's broad segment (position-only filter)
                int nB = nBW[warp]; if (nB > NSEGB) nB = NSEGB;
                const int bBase = warp * NSEGB, nBase = warp * NSEGN;
                int cntN = 0;
                for (int e = lane; ; e += 32) {
                    bool act = (e < nB);
                    unsigned am = __ballot_sync(0xFFFFFFFFu, act);
                    if (!am) break;
                    int p = 0, lo = 0, hi = 0;
                    float d2 = 1e30f, dx = 0.f, dy = 0.f;
                    if (act) {
                        p = candB[bBase + e]; lo = p >> 8; hi = p & 255;
                        float2 pl = posA[lo], ph = posA[hi];
                        dx = ph.x - pl.x; dy = ph.y - pl.y;
                        d2 = dx*dx + dy*dy;
                    }
                    bool pn = act && (d2 <= c2n);
                    unsigned mskn = __ballot_sync(0xFFFFFFFFu, pn);
                    if (pn) {
                        int sN = cntN + __popc(mskn & ((1u << lane) - 1u));
                        if (sN < NSEGN) candN[nBase + sN] = p;
                        if (d2 <= c2) {
                            float4 sl = bb0[lo], sh = bb0[hi];
                            float dvx = sh.z - sl.z, dvy = sh.w - sl.w;
                            if (dvx*dx + dvy*dy < 0.0f)
                                fold_ball_key(key, p, d2, two_r);
                        }
                    }
                    cntN += __popc(mskn);
                }
                if (lane == 0) nNW[warp] = cntN;
            } else {
                // event-time narrow scan of near list (positions first)
                int nN = nNW[warp]; if (nN > NSEGN) nN = NSEGN;
                const int nBase = warp * NSEGN;
                for (int e = lane; e < nN; e += 32) {
                    int p = candN[nBase + e];
                    int lo = p >> 8, hi = p & 255;
                    float2 pl = posA[lo], ph = posA[hi];
                    float dx = ph.x - pl.x, dy = ph.y - pl.y;
                    float d2 = dx*dx + dy*dy;
                    if (d2 <= c2) {
                        float4 sl = bb0[lo], sh = bb0[hi];
                        float dvx = sh.z - sl.z, dvy = sh.w - sl.w;
                        if (dvx*dx + dvy*dy < 0.0f)
                            fold_ball_key(key, p, d2, two_r);
                    }
                }
            }

            // wall candidates (gap-space, merged into same key; bit31 marks wall)
            if (half == 0) {
                float gs[4]; bool vs[4];
                gs[0] = me.x - rr;          vs[0] = me.z < 0.0f;
                gs[1] = 10.0f - me.x - rr;  vs[1] = me.z > 0.0f;
                gs[2] = me.y - rr;          vs[2] = me.w < 0.0f;
                gs[3] = 10.0f - me.y - rr;  vs[3] = me.w > 0.0f;
                #pragma unroll
                for (int w = 0; w < 4; ++w) {
                    if (vs[w]) {
                        unsigned u = __float_as_uint(gs[w]);
                        u = (u & 0x80000000u) ? ~u : (u | 0x80000000u);
                        unsigned long long k = ((unsigned long long)u << 32) |
                                               0x80000000u | (unsigned)(i0*4 + w);
                        if (k < key) key = k;
                    }
                }
            }

            // single 64-bit reduction: warp tree -> STS -> BAR -> 16-way butterfly
            #pragma unroll
            for (int off = 16; off > 0; off >>= 1) {
                unsigned long long o2 = __shfl_down_sync(0xFFFFFFFFu, key, off);
                if (o2 < key) key = o2;
            }
            if (lane == 0) redK[warp] = key;
            __syncthreads();                              // ---- BAR A ----

            if (tid == NTH-1) {
                if (bRb) {
                    float vm = vmaxW[0];
                    #pragma unroll
                    for (int w = 1; w < NWARP; ++w) vm = fmaxf(vm, vmaxW[w]);
                    sVmax2i = __float_as_int(vm);
                    int ovB = 0, ovN = 0;
                    #pragma unroll
                    for (int w = 0; w < NWARP; ++w) {
                        ovB |= (nBW[w] > NSEGB);
                        ovN |= (nNW[w] > NSEGN);
                    }
                    if (ovB) sOvB = 1;
                    sOvN = ovN;
                    sMotB = 0.0f; sMotN = 0.0f;
                } else if (nRb) {
                    int ovN = 0;
                    #pragma unroll
                    for (int w = 0; w < NWARP; ++w) ovN |= (nNW[w] > NSEGN);
                    sOvN = ovN;
                    sMotN = 0.0f;
                }
            }

            key = redK[lane & (NWARP-1)];
            #pragma unroll
            for (int off = 8; off > 0; off >>= 1) {
                unsigned long long o2 = __shfl_xor_sync(0xFFFFFFFFu, key, off);
                if (o2 < key) key = o2;
            }

            const unsigned gHi = (unsigned)(key >> 32);
            if (gHi == 0xFFFFFFFFu) break;                 // no candidates -> done
            unsigned gu = (gHi & 0x80000000u) ? (gHi ^ 0x80000000u) : ~gHi;
            const float gap = __uint_as_float(gu);
            if (gap > 0.05f) break;                        // no_event -> done

            const unsigned lo32 = (unsigned)key;
            const bool is_ball = (lo32 < 0x80000000u);

            // redundant decode + flags on ALL threads
            int iA, iB = 0, wsel = 0;
            float app;
            if (is_ball) {
                iA = (int)((lo32 >> 8) & 255u);
                iB = (int)(lo32 & 255u);
                float4 pi = bb0[iA], pj = bb0[iB];
                float nx = pj.x - pi.x, ny = pj.y - pi.y;
                float L = sqrtf(nx*nx + ny*ny);
                app = -(((pj.z - pi.z)*nx)/L + ((pj.w - pi.w)*ny)/L);
            } else {
                unsigned idx = lo32 & 0x7FFFFFFFu;
                iA = (int)(idx >> 2);
                wsel = (int)(idx & 3u);
                float4 pi = bb0[iA];
                app = fabsf(fmaxf(pi.z, pi.w));
            }
            const float t_ev  = t_c + gap / fmaxf(app, 1e-6f);
            const bool case_a = (gap <= 0.0f);
            const bool case_b = (!case_a) && (app > 1e-6f) && (t_ev < t_e);
            if (!case_a && !case_b) break;                 // done
            const float dte = case_b ? ((t_ev > t_c + 1e-10f) ? (t_ev - t_c) : 0.0f) : 0.0f;
            if (case_b) t_c = t_ev;

            if (is_ball) {
                if (tid < 2*HID) {
                    int sel = tid >> 6, o = tid & (HID-1);
                    const float4* S = sel ? bb0 : own;
                    float4 si = S[iA], sj = S[iB];
                    float six = fmaf(si.z, dte, si.x), siy = fmaf(si.w, dte, si.y);
                    float sjx = fmaf(sj.z, dte, sj.x), sjy = fmaf(sj.w, dte, sj.y);
                    float dx = sjx - six, dy = sjy - siy;
                    float dist = fmaxf(sqrtf(dx*dx + dy*dy), 1e-8f);
                    float nx = dx / dist, ny = dy / dist;
                    float ap = (sj.z - si.z)*nx + (sj.w - si.w)*ny;
                    float pre = dist*w1s[2*o] + ap*w1s[2*o+1] + b1s[o];
                    reinterpret_cast<float*>(h1q)[sel*HID + o] = silu_f(pre);
                    BAR_SYNC(3, 128);                     // h1 ready (warps 0-3)
                    const float4* H = &h1q[sel*16];
                    float a0 = 0.f, a1 = 0.f;
                    #pragma unroll 4
                    for (int k4 = 0; k4 < 16; k4 += 2) {
                        float4 w0 = w2q[(k4+0)*HID + o], hh0 = H[k4+0];
                        a0 = fmaf(w0.x,hh0.x,a0); a0 = fmaf(w0.y,hh0.y,a0);
                        a0 = fmaf(w0.z,hh0.z,a0); a0 = fmaf(w0.w,hh0.w,a0);
                        float4 w1v = w2q[(k4+1)*HID + o], hh1 = H[k4+1];
                        a1 = fmaf(w1v.x,hh1.x,a1); a1 = fmaf(w1v.y,hh1.y,a1);
                        a1 = fmaf(w1v.z,hh1.z,a1); a1 = fmaf(w1v.w,hh1.w,a1);
                    }
                    float acc = (b2s[o] + a0) + a1;
                    h2buf[sel*HID + o] = w3s[o] * silu_f(acc);
                    BAR_SYNC(3, 128);                     // h2 ready (warps 0-3)
                    if (warp == 0 || warp == 2) {
                        int sl = warp >> 1;
                        float v = h2buf[sl*HID + lane] + h2buf[sl*HID + 32 + lane];
                        #pragma unroll
                        for (int off = 16; off > 0; off >>= 1)
                            v += __shfl_down_sync(0xFFFFFFFFu, v, off);
                        if (lane == 0) {
                            float impv = v + b3v;
                            float4* S2 = sl ? bb0 : own;
                            float4 ti = S2[iA], tj = S2[iB];   // still pre-event values
                            float tix = fmaf(ti.z, dte, ti.x), tiy = fmaf(ti.w, dte, ti.y);
                            float tjx = fmaf(tj.z, dte, tj.x), tjy = fmaf(tj.w, dte, tj.y);
                            float ddx = tjx - tix, ddy = tjy - tiy;
                            float dst = fmaxf(sqrtf(ddx*ddx + ddy*ddy), 1e-8f);
                            float nnx = ddx/dst, nny = ddy/dst;
                            float niz = ti.z + impv*nnx, niw = ti.w + impv*nny;
                            float njz = tj.z - impv*nnx, njw = tj.w - impv*nny;
                            S2[iA] = make_float4(tix, tiy, niz, niw);
                            S2[iB] = make_float4(tjx, tjy, njz, njw);
                            if (sl == 1) {
                                posA[iA] = make_float2(tix, tiy);
                                posA[iB] = make_float2(tjx, tjy);
                                float sp = fmaxf(niz*niz + niw*niw, njz*njz + njw*njw);
                                atomicMax(&sVmax2i, __float_as_int(sp));
                            }
                        }
                    }
                } else if (tid < 384) {
                    int b = tid - 128;
                    if (dte != 0.0f && b != iA && b != iB) {
                        float4 v = own[b];
                        v.x = fmaf(v.z, dte, v.x); v.y = fmaf(v.w, dte, v.y);
                        own[b] = v;
                        float4 c = bb0[b];
                        c.x = fmaf(c.z, dte, c.x); c.y = fmaf(c.w, dte, c.y);
                        bb0[b] = c;
                        posA[b] = make_float2(c.x, c.y);
                    }
                } else if (tid == NTH-1) {
                    float dm = 2.0f * sqrtf(__int_as_float(sVmax2i)) * dte;
                    sMotB += dm; sMotN += dm;
                }
                __syncthreads();                          // ---- BAR E ----
            } else {
                // wall: compute result + integrate (b != iA) pre-barrier; write iA after
                float4 res; float pen = 0.0f;
                if (tid < 2) {
                    const float4 si = tid ? bb0[iA] : own[iA];
                    float six = fmaf(si.z, dte, si.x), siy = fmaf(si.w, dte, si.y);
                    float wnx = 0.0f, wny = 0.0f, wp = 0.0f;
                    if      (wsel == 0) { wnx =  1.0f; }
                    else if (wsel == 1) { wnx = -1.0f; wp = -10.0f; }
                    else if (wsel == 2) { wny =  1.0f; }
                    else                { wny = -1.0f; wp = -10.0f; }
                    float vn  = si.z*wnx + si.w*wny;
                    float nvx = si.z - 2.0f*vn*wnx;
                    float nvy = si.w - 2.0f*vn*wny;
                    float pn  = six*wnx + siy*wny;
                    pen = fmaxf(wp + rr - pn, 0.0f);
                    res = make_float4(six + pen*wnx, siy + pen*wny, nvx, nvy);
                } else if (tid >= 128 && tid < 384) {
                    int b = tid - 128;
                    if (dte != 0.0f && b != iA) {
                        float4 v = own[b];
                        v.x = fmaf(v.z, dte, v.x); v.y = fmaf(v.w, dte, v.y);
                        own[b] = v;
                        float4 c = bb0[b];
                        c.x = fmaf(c.z, dte, c.x); c.y = fmaf(c.w, dte, c.y);
                        bb0[b] = c;
                        posA[b] = make_float2(c.x, c.y);
                    }
                }
                __syncthreads();                          // ---- BAR W1 ----
                if (tid < 2) {
                    float4* S = tid ? bb0 : own;
                    S[iA] = res;
                    if (tid == 1) {
                        posA[iA] = make_float2(res.x, res.y);
                        float dm = 2.0f * sqrtf(__int_as_float(sVmax2i)) * dte + pen;
                        sMotB += dm; sMotN += dm;
                    }
                }
                __syncthreads();                          // ---- BAR W2 ----
            }
        }  // events

        // ---- step end ----
        __syncthreads();                                  // orders break-path reads vs writes
        const float dte2 = (t_e > t_c + 1e-10f) ? (t_e - t_c) : 0.0f;
        if (tid < NB) {
            float4 v = own[tid];
            v.x = fmaf(v.z, dte2, v.x); v.y = fmaf(v.w, dte2, v.y);
            own[tid] = v;
            float4 c = bb0[tid];
            c.x = fmaf(c.z, dte2, c.x); c.y = fmaf(c.w, dte2, c.y);
            bb0[tid] = c;
            posA[tid] = make_float2(c.x, c.y);
            reinterpret_cast<float4*>(g_out)[((long)(s+1)*BATCHN + bidx)*NB + tid] = v;
        }
        if (tid == 0) {
            float dm = 2.0f * sqrtf(__int_as_float(sVmax2i)) * dte2;
            sMotB += dm; sMotN += dm;
        }
        __syncthreads();
    }
}

extern "C" void kernel_launch(void* const* d_in, const int* in_sizes, int n_in,
                              void* d_out, int out_size) {
    (void)in_sizes; (void)n_in; (void)out_size;
    hybrid_rollout<<<BATCHN, NTH>>>(
        (const float*)d_in[0], (const float*)d_in[1],
        (const float*)d_in[2], (const float*)d_in[3],
        (const float*)d_in[4], (const float*)d_in[5],
        (const float*)d_in[6], (const float*)d_in[7],
        (float*)d_out);
}

// round 11
// speedup vs baseline: 1.1835x; 1.1835x over previous
#include <cuda_runtime.h>
#include <cuda_bf16.h>
#include <math.h>

#define NB 256
#define BATCHN 128
#define NSTEPS 100
#define MAXEV 5
#define HID 64
#define NTH 512
#define NWARP (NTH/32)
#define SEGCAP 385
#define MARGIN 1.0f

#define BAR_SYNC(id,cnt)   asm volatile("bar.sync %0, %1;"   :: "r"(id), "r"(cnt) : "memory")

__device__ __forceinline__ float silu_f(float x) {
    return x / (1.0f + expf(-x));
}

__device__ __forceinline__ void fold_ball_key(unsigned long long& key, int p, float d2, float two_r) {
    float gap = sqrtf(d2) - two_r;
    unsigned gu = __float_as_uint(gap);
    gu = (gu & 0x80000000u) ? ~gu : (gu | 0x80000000u);   // monotone float->uint
    unsigned long long k = ((unsigned long long)gu << 32) | (unsigned)p;
    if (k < key) key = k;
}

__global__ __launch_bounds__(NTH, 1)
void hybrid_rollout(const float* __restrict__ g_state,
                    const float* __restrict__ g_radii,
                    const float* __restrict__ g_W1,
                    const float* __restrict__ g_b1,
                    const float* __restrict__ g_W2,
                    const float* __restrict__ g_b2,
                    const float* __restrict__ g_W3,
                    const float* __restrict__ g_b3,
                    float* __restrict__ g_out)
{
    __shared__ float4 own[NB];                 // this block's batch element (AoS: apply path only)
    __shared__ float2 sPos[NB];                // batch-0 positions (SoA)
    __shared__ float2 sVel[NB];                // batch-0 velocities (SoA)
    __shared__ float4 w2q[16*HID];             // w2q[k4*HID+o] = W2[o][4k4..4k4+3]
    __shared__ float w1s[2*HID];
    __shared__ float b1s[HID], b2s[HID], w3s[HID];
    __shared__ float4 h1q[2*16];
    __shared__ float h2buf[2*HID];
    __shared__ unsigned long long redK[NWARP];
    __shared__ float vmaxW[NWARP];
    __shared__ int nCandW[NWARP];
    __shared__ int candList[NWARP*SEGCAP];     // per-warp segments, packed (lo<<8)|hi
    __shared__ int sVmax2i;
    __shared__ float sMotion;
    __shared__ int sOverflow;
    __shared__ float sb3, srr;

    const int tid  = threadIdx.x;
    const int bidx = blockIdx.x;
    const int i0   = tid & (NB-1);
    const int half = tid >> 8;
    const int lane = tid & 31;
    const int warp = tid >> 5;

    // ---- setup ----
    if (tid < NB) {
        float4 v = reinterpret_cast<const float4*>(g_state)[bidx*NB + tid];
        own[tid] = v;
        float4 c = reinterpret_cast<const float4*>(g_state)[tid];
        sPos[tid] = make_float2(c.x, c.y);
        sVel[tid] = make_float2(c.z, c.w);
        reinterpret_cast<float4*>(g_out)[bidx*NB + tid] = v;
    }
    for (int q = tid; q < 16*HID; q += NTH) {
        int o = q & 63, k4 = q >> 6;
        const float* src = g_W2 + o*HID + k4*4;
        w2q[q] = make_float4(src[0], src[1], src[2], src[3]);
    }
    if (tid < 2*HID) w1s[tid] = g_W1[tid];
    if (tid < HID) { b1s[tid] = g_b1[tid]; b2s[tid] = g_b2[tid]; w3s[tid] = g_W3[tid]; }
    if (tid == 0) {
        sb3 = g_b3[0]; srr = g_radii[0];
        sMotion = 1e30f; sVmax2i = 0; sOverflow = 0;
    }
    __syncthreads();

    const float rr    = srr;
    const float two_r = rr + rr;
    const float cut   = two_r + 0.051f;        // exact narrow cutoff (gap>0.05 -> done)
    const float c2    = cut * cut;
    const float cute  = cut + MARGIN;          // broad-phase cutoff
    const float c2e   = cute * cute;
    const float b3v   = sb3;

    for (int s = 0; s < NSTEPS; ++s) {
        const float t_s = (float)s * 0.05f;
        const float t_e = t_s + 0.05f;
        float t_c = t_s;

        for (int ev = 0; ev < MAXEV; ++ev) {
            // ================= P0: detection =================
            const bool rebuild = (sOverflow != 0) || (sMotion >= MARGIN);
            const float2 mp = sPos[i0];
            const float2 mv = sVel[i0];
            unsigned long long key = ~0ull;

            if (rebuild) {
                // warp-max of speed^2 (no atomics)
                float m = mv.x*mv.x + mv.y*mv.y;
                #pragma unroll
                for (int off = 16; off > 0; off >>= 1)
                    m = fmaxf(m, __shfl_down_sync(0xFFFFFFFFu, m, off));
                if (lane == 0) vmaxW[warp] = m;

                int cnt = 0;
                const int segBase = warp * SEGCAP;
                for (int d = 1 + half; d <= 128; d += 2) {
                    if (d == 128 && i0 >= 128) break;      // warp-uniform
                    int j = (i0 + d) & (NB-1);
                    float2 pj = sPos[j];
                    float dx = pj.x - mp.x, dy = pj.y - mp.y;
                    float d2 = dx*dx + dy*dy;
                    bool push = (d2 <= c2e);
                    unsigned msk = __ballot_sync(0xFFFFFFFFu, push);
                    if (push) {
                        int lo = (i0 < j) ? i0 : j;
                        int hi = (i0 < j) ? j : i0;
                        int p = (lo << 8) | hi;
                        int slot = cnt + __popc(msk & ((1u << lane) - 1u));
                        if (slot < SEGCAP) candList[segBase + slot] = p;
                        if (d2 <= c2) {
                            float2 vj = sVel[j];
                            float dvx = vj.x - mv.x, dvy = vj.y - mv.y;
                            if (dvx*dx + dvy*dy < 0.0f)
                                fold_ball_key(key, p, d2, two_r);
                        }
                    }
                    cnt += __popc(msk);
                }
                if (lane == 0) nCandW[warp] = cnt;
            } else {
                const int seg  = tid & (NWARP-1);
                const int e0   = tid >> 4;                 // 0..31
                int n = nCandW[seg]; if (n > SEGCAP) n = SEGCAP;
                const int base = seg * SEGCAP;
                for (int e = e0; e < n; e += 32) {
                    int p = candList[base + e];
                    int lo = p >> 8, hi = p & 255;
                    float2 pl = sPos[lo], ph = sPos[hi];
                    float dx = ph.x - pl.x, dy = ph.y - pl.y;
                    float d2 = dx*dx + dy*dy;
                    if (d2 <= c2) {
                        float2 vl = sVel[lo], vh = sVel[hi];
                        float dvx = vh.x - vl.x, dvy = vh.y - vl.y;
                        if (dvx*dx + dvy*dy < 0.0f)
                            fold_ball_key(key, p, d2, two_r);
                    }
                }
            }

            // wall candidates (gap-space, merged; bit31 marks wall)
            if (half == 0) {
                float gs[4]; bool vs[4];
                gs[0] = mp.x - rr;          vs[0] = mv.x < 0.0f;
                gs[1] = 10.0f - mp.x - rr;  vs[1] = mv.x > 0.0f;
                gs[2] = mp.y - rr;          vs[2] = mv.y < 0.0f;
                gs[3] = 10.0f - mp.y - rr;  vs[3] = mv.y > 0.0f;
                #pragma unroll
                for (int w = 0; w < 4; ++w) {
                    if (vs[w]) {
                        unsigned u = __float_as_uint(gs[w]);
                        u = (u & 0x80000000u) ? ~u : (u | 0x80000000u);
                        unsigned long long k = ((unsigned long long)u << 32) |
                                               0x80000000u | (unsigned)(i0*4 + w);
                        if (k < key) key = k;
                    }
                }
            }

            // single 64-bit reduction: warp tree -> STS -> BAR -> 16-way butterfly
            #pragma unroll
            for (int off = 16; off > 0; off >>= 1) {
                unsigned long long o2 = __shfl_down_sync(0xFFFFFFFFu, key, off);
                if (o2 < key) key = o2;
            }
            if (lane == 0) redK[warp] = key;
            __syncthreads();                              // ---- BAR A ----

            if (rebuild && tid == NTH-1) {
                float vm = vmaxW[0];
                #pragma unroll
                for (int w = 1; w < NWARP; ++w) vm = fmaxf(vm, vmaxW[w]);
                sVmax2i = __float_as_int(vm);
                int ov = 0;
                #pragma unroll
                for (int w = 0; w < NWARP; ++w) ov |= (nCandW[w] > SEGCAP);
                if (ov) sOverflow = 1;
                sMotion = 0.0f;
            }

            key = redK[lane & (NWARP-1)];
            #pragma unroll
            for (int off = 8; off > 0; off >>= 1) {
                unsigned long long o2 = __shfl_xor_sync(0xFFFFFFFFu, key, off);
                if (o2 < key) key = o2;
            }

            const unsigned gHi = (unsigned)(key >> 32);
            if (gHi == 0xFFFFFFFFu) break;                 // no candidates -> done
            unsigned gu = (gHi & 0x80000000u) ? (gHi ^ 0x80000000u) : ~gHi;
            const float gap = __uint_as_float(gu);
            if (gap > 0.05f) break;                        // no_event -> done

            const unsigned lo32 = (unsigned)key;
            const bool is_ball = (lo32 < 0x80000000u);

            // redundant decode + flags on ALL threads
            int iA, iB = 0, wsel = 0;
            float app;
            if (is_ball) {
                iA = (int)((lo32 >> 8) & 255u);
                iB = (int)(lo32 & 255u);
                float2 pi = sPos[iA], pj = sPos[iB];
                float2 vi = sVel[iA], vj = sVel[iB];
                float nx = pj.x - pi.x, ny = pj.y - pi.y;
                float L = sqrtf(nx*nx + ny*ny);
                app = -(((vj.x - vi.x)*nx)/L + ((vj.y - vi.y)*ny)/L);
            } else {
                unsigned idx = lo32 & 0x7FFFFFFFu;
                iA = (int)(idx >> 2);
                wsel = (int)(idx & 3u);
                float2 vi = sVel[iA];
                app = fabsf(fmaxf(vi.x, vi.y));
            }
            const float t_ev  = t_c + gap / fmaxf(app, 1e-6f);
            const bool case_a = (gap <= 0.0f);
            const bool case_b = (!case_a) && (app > 1e-6f) && (t_ev < t_e);
            if (!case_a && !case_b) break;                 // done
            const float dte = case_b ? ((t_ev > t_c + 1e-10f) ? (t_ev - t_c) : 0.0f) : 0.0f;
            if (case_b) t_c = t_ev;

            if (is_ball) {
                // warps 0-3: MLP; warps 4-11: integrate (skip iA,iB); thread 511: sMotion
                if (tid < 2*HID) {
                    int sel = tid >> 6, o = tid & (HID-1);
                    float4 si, sj;
                    if (sel) {
                        float2 p1 = sPos[iA], v1 = sVel[iA];
                        float2 p2 = sPos[iB], v2 = sVel[iB];
                        si = make_float4(p1.x, p1.y, v1.x, v1.y);
                        sj = make_float4(p2.x, p2.y, v2.x, v2.y);
                    } else {
                        si = own[iA]; sj = own[iB];
                    }
                    float six = fmaf(si.z, dte, si.x), siy = fmaf(si.w, dte, si.y);
                    float sjx = fmaf(sj.z, dte, sj.x), sjy = fmaf(sj.w, dte, sj.y);
                    float dx = sjx - six, dy = sjy - siy;
                    float dist = fmaxf(sqrtf(dx*dx + dy*dy), 1e-8f);
                    float nx = dx / dist, ny = dy / dist;
                    float ap = (sj.z - si.z)*nx + (sj.w - si.w)*ny;
                    float pre = dist*w1s[2*o] + ap*w1s[2*o+1] + b1s[o];
                    reinterpret_cast<float*>(h1q)[sel*HID + o] = silu_f(pre);
                    BAR_SYNC(3, 128);                     // h1 ready (warps 0-3)
                    const float4* H = &h1q[sel*16];
                    float a0 = 0.f, a1 = 0.f;
                    #pragma unroll 4
                    for (int k4 = 0; k4 < 16; k4 += 2) {
                        float4 w0 = w2q[(k4+0)*HID + o], hh0 = H[k4+0];
                        a0 = fmaf(w0.x,hh0.x,a0); a0 = fmaf(w0.y,hh0.y,a0);
                        a0 = fmaf(w0.z,hh0.z,a0); a0 = fmaf(w0.w,hh0.w,a0);
                        float4 w1v = w2q[(k4+1)*HID + o], hh1 = H[k4+1];
                        a1 = fmaf(w1v.x,hh1.x,a1); a1 = fmaf(w1v.y,hh1.y,a1);
                        a1 = fmaf(w1v.z,hh1.z,a1); a1 = fmaf(w1v.w,hh1.w,a1);
                    }
                    float acc = (b2s[o] + a0) + a1;
                    h2buf[sel*HID + o] = w3s[o] * silu_f(acc);
                    BAR_SYNC(3, 128);                     // h2 ready (warps 0-3)
                    if (warp == 0 || warp == 2) {
                        int sl = warp >> 1;
                        float v = h2buf[sl*HID + lane] + h2buf[sl*HID + 32 + lane];
                        #pragma unroll
                        for (int off = 16; off > 0; off >>= 1)
                            v += __shfl_down_sync(0xFFFFFFFFu, v, off);
                        if (lane == 0) {
                            float impv = v + b3v;
                            float4 ti, tj;
                            if (sl) {
                                float2 p1 = sPos[iA], v1 = sVel[iA];
                                float2 p2 = sPos[iB], v2 = sVel[iB];
                                ti = make_float4(p1.x, p1.y, v1.x, v1.y);
                                tj = make_float4(p2.x, p2.y, v2.x, v2.y);
                            } else {
                                ti = own[iA]; tj = own[iB];
                            }
                            float tix = fmaf(ti.z, dte, ti.x), tiy = fmaf(ti.w, dte, ti.y);
                            float tjx = fmaf(tj.z, dte, tj.x), tjy = fmaf(tj.w, dte, tj.y);
                            float ddx = tjx - tix, ddy = tjy - tiy;
                            float dst = fmaxf(sqrtf(ddx*ddx + ddy*ddy), 1e-8f);
                            float nnx = ddx/dst, nny = ddy/dst;
                            float niz = ti.z + impv*nnx, niw = ti.w + impv*nny;
                            float njz = tj.z - impv*nnx, njw = tj.w - impv*nny;
                            if (sl) {
                                sPos[iA] = make_float2(tix, tiy);
                                sPos[iB] = make_float2(tjx, tjy);
                                sVel[iA] = make_float2(niz, niw);
                                sVel[iB] = make_float2(njz, njw);
                                float sp = fmaxf(niz*niz + niw*niw, njz*njz + njw*njw);
                                atomicMax(&sVmax2i, __float_as_int(sp));
                            } else {
                                own[iA] = make_float4(tix, tiy, niz, niw);
                                own[iB] = make_float4(tjx, tjy, njz, njw);
                            }
                        }
                    }
                } else if (tid < 384) {
                    int b = tid - 128;
                    if (dte != 0.0f && b != iA && b != iB) {
                        float4 v = own[b];
                        v.x = fmaf(v.z, dte, v.x); v.y = fmaf(v.w, dte, v.y);
                        own[b] = v;
                        float2 p = sPos[b], vv = sVel[b];
                        sPos[b] = make_float2(fmaf(vv.x, dte, p.x), fmaf(vv.y, dte, p.y));
                    }
                } else if (tid == NTH-1) {
                    sMotion += 2.0f * sqrtf(__int_as_float(sVmax2i)) * dte;
                }
                __syncthreads();                          // ---- BAR E ----
            } else {
                // wall: compute result + integrate (b != iA) pre-barrier; write iA after
                float4 res; float pen = 0.0f;
                if (tid < 2) {
                    float4 si;
                    if (tid) {
                        float2 p1 = sPos[iA], v1 = sVel[iA];
                        si = make_float4(p1.x, p1.y, v1.x, v1.y);
                    } else {
                        si = own[iA];
                    }
                    float six = fmaf(si.z, dte, si.x), siy = fmaf(si.w, dte, si.y);
                    float wnx = 0.0f, wny = 0.0f, wp = 0.0f;
                    if      (wsel == 0) { wnx =  1.0f; }
                    else if (wsel == 1) { wnx = -1.0f; wp = -10.0f; }
                    else if (wsel == 2) { wny =  1.0f; }
                    else                { wny = -1.0f; wp = -10.0f; }
                    float vn  = si.z*wnx + si.w*wny;
                    float nvx = si.z - 2.0f*vn*wnx;
                    float nvy = si.w - 2.0f*vn*wny;
                    float pn  = six*wnx + siy*wny;
                    pen = fmaxf(wp + rr - pn, 0.0f);
                    res = make_float4(six + pen*wnx, siy + pen*wny, nvx, nvy);
                } else if (tid >= 128 && tid < 384) {
                    int b = tid - 128;
                    if (dte != 0.0f && b != iA) {
                        float4 v = own[b];
                        v.x = fmaf(v.z, dte, v.x); v.y = fmaf(v.w, dte, v.y);
                        own[b] = v;
                        float2 p = sPos[b], vv = sVel[b];
                        sPos[b] = make_float2(fmaf(vv.x, dte, p.x), fmaf(vv.y, dte, p.y));
                    }
                }
                __syncthreads();                          // ---- BAR W1 ----
                if (tid < 2) {
                    if (tid) {
                        sPos[iA] = make_float2(res.x, res.y);
                        sVel[iA] = make_float2(res.z, res.w);
                        sMotion += 2.0f * sqrtf(__int_as_float(sVmax2i)) * dte + pen;
                    } else {
                        own[iA] = res;
                    }
                }
                __syncthreads();                          // ---- BAR W2 ----
            }
        }  // events

        // ---- step end ----
        __syncthreads();                                  // orders break-path reads vs writes
        const float dte2 = (t_e > t_c + 1e-10f) ? (t_e - t_c) : 0.0f;
        if (tid < NB) {
            float4 v = own[tid];
            v.x = fmaf(v.z, dte2, v.x); v.y = fmaf(v.w, dte2, v.y);
            own[tid] = v;
            float2 p = sPos[tid], vv = sVel[tid];
            sPos[tid] = make_float2(fmaf(vv.x, dte2, p.x), fmaf(vv.y, dte2, p.y));
            reinterpret_cast<float4*>(g_out)[((long)(s+1)*BATCHN + bidx)*NB + tid] = v;
        }
        if (tid == 0)
            sMotion += 2.0f * sqrtf(__int_as_float(sVmax2i)) * dte2;
        __syncthreads();
    }
}

extern "C" void kernel_launch(void* const* d_in, const int* in_sizes, int n_in,
                              void* d_out, int out_size) {
    (void)in_sizes; (void)n_in; (void)out_size;
    hybrid_rollout<<<BATCHN, NTH>>>(
        (const float*)d_in[0], (const float*)d_in[1],
        (const float*)d_in[2], (const float*)d_in[3],
        (const float*)d_in[4], (const float*)d_in[5],
        (const float*)d_in[6], (const float*)d_in[7],
        (float*)d_out);
}

// round 13
// speedup vs baseline: 1.2962x; 1.0952x over previous
#include <cuda_runtime.h>
#include <cuda_bf16.h>
#include <math.h>

#define NB 256
#define BATCHN 128
#define NSTEPS 100
#define MAXEV 5
#define HID 64
#define NTH 512
#define NWARP (NTH/32)
#define SEGCAP 385
#define MARGIN 1.0f

#define BAR_SYNC(id,cnt)   asm volatile("bar.sync %0, %1;"   :: "r"(id), "r"(cnt) : "memory")

__device__ __forceinline__ float silu_f(float x) {
    return __fdividef(x, 1.0f + __expf(-x));
}

// lexicographic 64-bit min across full warp via 2x REDUX.MIN.u32
__device__ __forceinline__ unsigned long long warp_min_key(unsigned long long key) {
    unsigned hi = (unsigned)(key >> 32), lo = (unsigned)key;
    unsigned mh = __reduce_min_sync(0xFFFFFFFFu, hi);
    unsigned cl = (hi == mh) ? lo : 0xFFFFFFFFu;
    unsigned ml = __reduce_min_sync(0xFFFFFFFFu, cl);
    return ((unsigned long long)mh << 32) | ml;
}

__device__ __forceinline__ void fold_ball_key(unsigned long long& key, int p, float d2, float two_r) {
    float gap = sqrtf(d2) - two_r;
    unsigned gu = __float_as_uint(gap);
    gu = (gu & 0x80000000u) ? ~gu : (gu | 0x80000000u);   // monotone float->uint
    unsigned long long k = ((unsigned long long)gu << 32) | (unsigned)p;
    if (k < key) key = k;
}

__global__ __launch_bounds__(NTH, 1)
void hybrid_rollout(const float* __restrict__ g_state,
                    const float* __restrict__ g_radii,
                    const float* __restrict__ g_W1,
                    const float* __restrict__ g_b1,
                    const float* __restrict__ g_W2,
                    const float* __restrict__ g_b2,
                    const float* __restrict__ g_W3,
                    const float* __restrict__ g_b3,
                    float* __restrict__ g_out)
{
    __shared__ float4 own[NB];                 // this block's batch element (AoS: apply path only)
    __shared__ float2 sPos[NB];                // batch-0 positions (SoA)
    __shared__ float2 sVel[NB];                // batch-0 velocities (SoA)
    __shared__ float4 w2q[16*HID];             // w2q[k4*HID+o] = W2[o][4k4..4k4+3]
    __shared__ float w1s[2*HID];
    __shared__ float b1s[HID], b2s[HID], w3s[HID];
    __shared__ float4 h1q[2*16];
    __shared__ float h2buf[2*HID];
    __shared__ unsigned long long redK[NWARP];
    __shared__ float vmaxW[NWARP];
    __shared__ int nCandW[NWARP];
    __shared__ int candList[NWARP*SEGCAP];     // per-warp segments, packed (lo<<8)|hi
    __shared__ int sVmax2i;
    __shared__ float sMotion;
    __shared__ int sOverflow;
    __shared__ float sb3, srr;

    const int tid  = threadIdx.x;
    const int bidx = blockIdx.x;
    const int i0   = tid & (NB-1);
    const int half = tid >> 8;
    const int lane = tid & 31;
    const int warp = tid >> 5;

    // ---- setup ----
    if (tid < NB) {
        float4 v = reinterpret_cast<const float4*>(g_state)[bidx*NB + tid];
        own[tid] = v;
        float4 c = reinterpret_cast<const float4*>(g_state)[tid];
        sPos[tid] = make_float2(c.x, c.y);
        sVel[tid] = make_float2(c.z, c.w);
        reinterpret_cast<float4*>(g_out)[bidx*NB + tid] = v;
    }
    for (int q = tid; q < 16*HID; q += NTH) {
        int o = q & 63, k4 = q >> 6;
        const float* src = g_W2 + o*HID + k4*4;
        w2q[q] = make_float4(src[0], src[1], src[2], src[3]);
    }
    if (tid < 2*HID) w1s[tid] = g_W1[tid];
    if (tid < HID) { b1s[tid] = g_b1[tid]; b2s[tid] = g_b2[tid]; w3s[tid] = g_W3[tid]; }
    if (tid == 0) {
        sb3 = g_b3[0]; srr = g_radii[0];
        sMotion = 1e30f; sVmax2i = 0; sOverflow = 0;
    }
    __syncthreads();

    const float rr    = srr;
    const float two_r = rr + rr;
    const float cut   = two_r + 0.051f;        // exact narrow cutoff (gap>0.05 -> done)
    const float c2    = cut * cut;
    const float cute  = cut + MARGIN;          // broad-phase cutoff
    const float c2e   = cute * cute;
    const float b3v   = sb3;

    for (int s = 0; s < NSTEPS; ++s) {
        const float t_s = (float)s * 0.05f;
        const float t_e = t_s + 0.05f;
        float t_c = t_s;

        for (int ev = 0; ev < MAXEV; ++ev) {
            // ================= P0: detection =================
            const bool rebuild = (sOverflow != 0) || (sMotion >= MARGIN);
            const float2 mp = sPos[i0];
            const float2 mv = sVel[i0];
            unsigned long long key = ~0ull;

            if (rebuild) {
                // warp-max of speed^2 (no atomics)
                float m = mv.x*mv.x + mv.y*mv.y;
                #pragma unroll
                for (int off = 16; off > 0; off >>= 1)
                    m = fmaxf(m, __shfl_down_sync(0xFFFFFFFFu, m, off));
                if (lane == 0) vmaxW[warp] = m;

                int cnt = 0;
                const int segBase = warp * SEGCAP;
                for (int d = 1 + half; d <= 128; d += 2) {
                    if (d == 128 && i0 >= 128) break;      // warp-uniform
                    int j = (i0 + d) & (NB-1);
                    float2 pj = sPos[j];
                    float dx = pj.x - mp.x, dy = pj.y - mp.y;
                    float d2 = dx*dx + dy*dy;
                    bool push = (d2 <= c2e);
                    unsigned msk = __ballot_sync(0xFFFFFFFFu, push);
                    if (push) {
                        int lo = (i0 < j) ? i0 : j;
                        int hi = (i0 < j) ? j : i0;
                        int p = (lo << 8) | hi;
                        int slot = cnt + __popc(msk & ((1u << lane) - 1u));
                        if (slot < SEGCAP) candList[segBase + slot] = p;
                        if (d2 <= c2) {
                            float2 vj = sVel[j];
                            float dvx = vj.x - mv.x, dvy = vj.y - mv.y;
                            if (dvx*dx + dvy*dy < 0.0f)
                                fold_ball_key(key, p, d2, two_r);
                        }
                    }
                    cnt += __popc(msk);
                }
                if (lane == 0) nCandW[warp] = cnt;
            } else {
                const int seg  = tid & (NWARP-1);
                const int e0   = tid >> 4;                 // 0..31
                int n = nCandW[seg]; if (n > SEGCAP) n = SEGCAP;
                const int base = seg * SEGCAP;
                for (int e = e0; e < n; e += 32) {
                    int p = candList[base + e];
                    int lo = p >> 8, hi = p & 255;
                    float2 pl = sPos[lo], ph = sPos[hi];
                    float dx = ph.x - pl.x, dy = ph.y - pl.y;
                    float d2 = dx*dx + dy*dy;
                    if (d2 <= c2) {
                        float2 vl = sVel[lo], vh = sVel[hi];
                        float dvx = vh.x - vl.x, dvy = vh.y - vl.y;
                        if (dvx*dx + dvy*dy < 0.0f)
                            fold_ball_key(key, p, d2, two_r);
                    }
                }
            }

            // wall candidates (gap-space, merged; bit31 marks wall)
            if (half == 0) {
                float gs[4]; bool vs[4];
                gs[0] = mp.x - rr;          vs[0] = mv.x < 0.0f;
                gs[1] = 10.0f - mp.x - rr;  vs[1] = mv.x > 0.0f;
                gs[2] = mp.y - rr;          vs[2] = mv.y < 0.0f;
                gs[3] = 10.0f - mp.y - rr;  vs[3] = mv.y > 0.0f;
                #pragma unroll
                for (int w = 0; w < 4; ++w) {
                    if (vs[w]) {
                        unsigned u = __float_as_uint(gs[w]);
                        u = (u & 0x80000000u) ? ~u : (u | 0x80000000u);
                        unsigned long long k = ((unsigned long long)u << 32) |
                                               0x80000000u | (unsigned)(i0*4 + w);
                        if (k < key) key = k;
                    }
                }
            }

            // warp REDUX min -> STS -> BAR -> block REDUX min over 16 slots
            key = warp_min_key(key);
            if (lane == 0) redK[warp] = key;
            __syncthreads();                              // ---- BAR A ----

            if (rebuild && tid == NTH-1) {
                float vm = vmaxW[0];
                #pragma unroll
                for (int w = 1; w < NWARP; ++w) vm = fmaxf(vm, vmaxW[w]);
                sVmax2i = __float_as_int(vm);
                int ov = 0;
                #pragma unroll
                for (int w = 0; w < NWARP; ++w) ov |= (nCandW[w] > SEGCAP);
                if (ov) sOverflow = 1;
                sMotion = 0.0f;
            }

            key = warp_min_key(redK[lane & (NWARP-1)]);

            const unsigned gHi = (unsigned)(key >> 32);
            if (gHi == 0xFFFFFFFFu) break;                 // no candidates -> done
            unsigned gu = (gHi & 0x80000000u) ? (gHi ^ 0x80000000u) : ~gHi;
            const float gap = __uint_as_float(gu);
            if (gap > 0.05f) break;                        // no_event -> done

            const unsigned lo32 = (unsigned)key;
            const bool is_ball = (lo32 < 0x80000000u);

            // redundant decode + flags on ALL threads
            int iA, iB = 0, wsel = 0;
            float app;
            if (is_ball) {
                iA = (int)((lo32 >> 8) & 255u);
                iB = (int)(lo32 & 255u);
                float2 pi = sPos[iA], pj = sPos[iB];
                float2 vi = sVel[iA], vj = sVel[iB];
                float nx = pj.x - pi.x, ny = pj.y - pi.y;
                float L = sqrtf(nx*nx + ny*ny);
                float rL = __fdividef(1.0f, L);
                app = -(((vj.x - vi.x)*nx)*rL + ((vj.y - vi.y)*ny)*rL);
            } else {
                unsigned idx = lo32 & 0x7FFFFFFFu;
                iA = (int)(idx >> 2);
                wsel = (int)(idx & 3u);
                float2 vi = sVel[iA];
                app = fabsf(fmaxf(vi.x, vi.y));
            }
            const float t_ev  = t_c + __fdividef(gap, fmaxf(app, 1e-6f));
            const bool case_a = (gap <= 0.0f);
            const bool case_b = (!case_a) && (app > 1e-6f) && (t_ev < t_e);
            if (!case_a && !case_b) break;                 // done
            const float dte = case_b ? ((t_ev > t_c + 1e-10f) ? (t_ev - t_c) : 0.0f) : 0.0f;
            if (case_b) t_c = t_ev;

            if (is_ball) {
                // warps 0-3: MLP; warps 4-11: integrate (skip iA,iB); thread 511: sMotion
                if (tid < 2*HID) {
                    int sel = tid >> 6, o = tid & (HID-1);
                    float4 si, sj;
                    if (sel) {
                        float2 p1 = sPos[iA], v1 = sVel[iA];
                        float2 p2 = sPos[iB], v2 = sVel[iB];
                        si = make_float4(p1.x, p1.y, v1.x, v1.y);
                        sj = make_float4(p2.x, p2.y, v2.x, v2.y);
                    } else {
                        si = own[iA]; sj = own[iB];
                    }
                    float six = fmaf(si.z, dte, si.x), siy = fmaf(si.w, dte, si.y);
                    float sjx = fmaf(sj.z, dte, sj.x), sjy = fmaf(sj.w, dte, sj.y);
                    float dx = sjx - six, dy = sjy - siy;
                    float dist = fmaxf(sqrtf(dx*dx + dy*dy), 1e-8f);
                    float ri = __fdividef(1.0f, dist);
                    float nx = dx * ri, ny = dy * ri;
                    float ap = (sj.z - si.z)*nx + (sj.w - si.w)*ny;
                    float pre = dist*w1s[2*o] + ap*w1s[2*o+1] + b1s[o];
                    reinterpret_cast<float*>(h1q)[sel*HID + o] = silu_f(pre);
                    BAR_SYNC(3, 128);                     // h1 ready (warps 0-3)
                    const float4* H = &h1q[sel*16];
                    float a0 = 0.f, a1 = 0.f, a2 = 0.f, a3 = 0.f;
                    #pragma unroll 2
                    for (int k4 = 0; k4 < 16; k4 += 4) {
                        float4 w0 = w2q[(k4+0)*HID + o], hh0 = H[k4+0];
                        a0 = fmaf(w0.x,hh0.x,a0); a0 = fmaf(w0.y,hh0.y,a0);
                        a0 = fmaf(w0.z,hh0.z,a0); a0 = fmaf(w0.w,hh0.w,a0);
                        float4 w1v = w2q[(k4+1)*HID + o], hh1 = H[k4+1];
                        a1 = fmaf(w1v.x,hh1.x,a1); a1 = fmaf(w1v.y,hh1.y,a1);
                        a1 = fmaf(w1v.z,hh1.z,a1); a1 = fmaf(w1v.w,hh1.w,a1);
                        float4 w2v = w2q[(k4+2)*HID + o], hh2 = H[k4+2];
                        a2 = fmaf(w2v.x,hh2.x,a2); a2 = fmaf(w2v.y,hh2.y,a2);
                        a2 = fmaf(w2v.z,hh2.z,a2); a2 = fmaf(w2v.w,hh2.w,a2);
                        float4 w3v = w2q[(k4+3)*HID + o], hh3 = H[k4+3];
                        a3 = fmaf(w3v.x,hh3.x,a3); a3 = fmaf(w3v.y,hh3.y,a3);
                        a3 = fmaf(w3v.z,hh3.z,a3); a3 = fmaf(w3v.w,hh3.w,a3);
                    }
                    float acc = ((b2s[o] + a0) + a1) + (a2 + a3);
                    h2buf[sel*HID + o] = w3s[o] * silu_f(acc);
                    BAR_SYNC(3, 128);                     // h2 ready (warps 0-3)
                    if (warp == 0 || warp == 2) {
                        int sl = warp >> 1;
                        float v = h2buf[sl*HID + lane] + h2buf[sl*HID + 32 + lane];
                        #pragma unroll
                        for (int off = 16; off > 0; off >>= 1)
                            v += __shfl_down_sync(0xFFFFFFFFu, v, off);
                        if (lane == 0) {
                            float impv = v + b3v;
                            float4 ti, tj;
                            if (sl) {
                                float2 p1 = sPos[iA], v1 = sVel[iA];
                                float2 p2 = sPos[iB], v2 = sVel[iB];
                                ti = make_float4(p1.x, p1.y, v1.x, v1.y);
                                tj = make_float4(p2.x, p2.y, v2.x, v2.y);
                            } else {
                                ti = own[iA]; tj = own[iB];
                            }
                            float tix = fmaf(ti.z, dte, ti.x), tiy = fmaf(ti.w, dte, ti.y);
                            float tjx = fmaf(tj.z, dte, tj.x), tjy = fmaf(tj.w, dte, tj.y);
                            float ddx = tjx - tix, ddy = tjy - tiy;
                            float dst = fmaxf(sqrtf(ddx*ddx + ddy*ddy), 1e-8f);
                            float rst = __fdividef(1.0f, dst);
                            float nnx = ddx*rst, nny = ddy*rst;
                            float niz = ti.z + impv*nnx, niw = ti.w + impv*nny;
                            float njz = tj.z - impv*nnx, njw = tj.w - impv*nny;
                            if (sl) {
                                sPos[iA] = make_float2(tix, tiy);
                                sPos[iB] = make_float2(tjx, tjy);
                                sVel[iA] = make_float2(niz, niw);
                                sVel[iB] = make_float2(njz, njw);
                                float sp = fmaxf(niz*niz + niw*niw, njz*njz + njw*njw);
                                atomicMax(&sVmax2i, __float_as_int(sp));
                            } else {
                                own[iA] = make_float4(tix, tiy, niz, niw);
                                own[iB] = make_float4(tjx, tjy, njz, njw);
                            }
                        }
                    }
                } else if (tid < 384) {
                    int b = tid - 128;
                    if (dte != 0.0f && b != iA && b != iB) {
                        float4 v = own[b];
                        v.x = fmaf(v.z, dte, v.x); v.y = fmaf(v.w, dte, v.y);
                        own[b] = v;
                        float2 p = sPos[b], vv = sVel[b];
                        sPos[b] = make_float2(fmaf(vv.x, dte, p.x), fmaf(vv.y, dte, p.y));
                    }
                } else if (tid == NTH-1) {
                    sMotion += 2.0f * sqrtf(__int_as_float(sVmax2i)) * dte;
                }
                __syncthreads();                          // ---- BAR E ----
            } else {
                // wall: compute result + integrate (b != iA) pre-barrier; write iA after
                float4 res; float pen = 0.0f;
                if (tid < 2) {
                    float4 si;
                    if (tid) {
                        float2 p1 = sPos[iA], v1 = sVel[iA];
                        si = make_float4(p1.x, p1.y, v1.x, v1.y);
                    } else {
                        si = own[iA];
                    }
                    float six = fmaf(si.z, dte, si.x), siy = fmaf(si.w, dte, si.y);
                    float wnx = 0.0f, wny = 0.0f, wp = 0.0f;
                    if      (wsel == 0) { wnx =  1.0f; }
                    else if (wsel == 1) { wnx = -1.0f; wp = -10.0f; }
                    else if (wsel == 2) { wny =  1.0f; }
                    else                { wny = -1.0f; wp = -10.0f; }
                    float vn  = si.z*wnx + si.w*wny;
                    float nvx = si.z - 2.0f*vn*wnx;
                    float nvy = si.w - 2.0f*vn*wny;
                    float pn  = six*wnx + siy*wny;
                    pen = fmaxf(wp + rr - pn, 0.0f);
                    res = make_float4(six + pen*wnx, siy + pen*wny, nvx, nvy);
                } else if (tid >= 128 && tid < 384) {
                    int b = tid - 128;
                    if (dte != 0.0f && b != iA) {
                        float4 v = own[b];
                        v.x = fmaf(v.z, dte, v.x); v.y = fmaf(v.w, dte, v.y);
                        own[b] = v;
                        float2 p = sPos[b], vv = sVel[b];
                        sPos[b] = make_float2(fmaf(vv.x, dte, p.x), fmaf(vv.y, dte, p.y));
                    }
                }
                __syncthreads();                          // ---- BAR W1 ----
                if (tid < 2) {
                    if (tid) {
                        sPos[iA] = make_float2(res.x, res.y);
                        sVel[iA] = make_float2(res.z, res.w);
                        sMotion += 2.0f * sqrtf(__int_as_float(sVmax2i)) * dte + pen;
                    } else {
                        own[iA] = res;
                    }
                }
                __syncthreads();                          // ---- BAR W2 ----
            }
        }  // events

        // ---- step end ----
        __syncthreads();                                  // orders break-path reads vs writes
        const float dte2 = (t_e > t_c + 1e-10f) ? (t_e - t_c) : 0.0f;
        if (tid < NB) {
            float4 v = own[tid];
            v.x = fmaf(v.z, dte2, v.x); v.y = fmaf(v.w, dte2, v.y);
            own[tid] = v;
            float2 p = sPos[tid], vv = sVel[tid];
            sPos[tid] = make_float2(fmaf(vv.x, dte2, p.x), fmaf(vv.y, dte2, p.y));
            reinterpret_cast<float4*>(g_out)[((long)(s+1)*BATCHN + bidx)*NB + tid] = v;
        }
        if (tid == 0)
            sMotion += 2.0f * sqrtf(__int_as_float(sVmax2i)) * dte2;
        __syncthreads();
    }
}

extern "C" void kernel_launch(void* const* d_in, const int* in_sizes, int n_in,
                              void* d_out, int out_size) {
    (void)in_sizes; (void)n_in; (void)out_size;
    hybrid_rollout<<<BATCHN, NTH>>>(
        (const float*)d_in[0], (const float*)d_in[1],
        (const float*)d_in[2], (const float*)d_in[3],
        (const float*)d_in[4], (const float*)d_in[5],
        (const float*)d_in[6], (const float*)d_in[7],
        (float*)d_out);
}

// round 14
// speedup vs baseline: 1.3620x; 1.0507x over previous
#include <cuda_runtime.h>
#include <cuda_bf16.h>
#include <math.h>

#define NB 256
#define BATCHN 128
#define NSTEPS 100
#define MAXEV 5
#define HID 64
#define NTH 512
#define NWARP (NTH/32)
#define SEGCAP 385
#define MARGIN 1.0f

#define BAR_SYNC(id,cnt)   asm volatile("bar.sync %0, %1;"   :: "r"(id), "r"(cnt) : "memory")

__device__ __forceinline__ float silu_f(float x) {
    return __fdividef(x, 1.0f + __expf(-x));
}

// lexicographic 64-bit min across full warp via 2x REDUX.MIN.u32
__device__ __forceinline__ unsigned long long warp_min_key(unsigned long long key) {
    unsigned hi = (unsigned)(key >> 32), lo = (unsigned)key;
    unsigned mh = __reduce_min_sync(0xFFFFFFFFu, hi);
    unsigned cl = (hi == mh) ? lo : 0xFFFFFFFFu;
    unsigned ml = __reduce_min_sync(0xFFFFFFFFu, cl);
    return ((unsigned long long)mh << 32) | ml;
}

__device__ __forceinline__ void fold_ball_key(unsigned long long& key, int p, float d2, float two_r) {
    float gap = sqrtf(d2) - two_r;
    unsigned gu = __float_as_uint(gap);
    gu = (gu & 0x80000000u) ? ~gu : (gu | 0x80000000u);   // monotone float->uint
    unsigned long long k = ((unsigned long long)gu << 32) | (unsigned)p;
    if (k < key) key = k;
}

__global__ __launch_bounds__(NTH, 1)
void hybrid_rollout(const float* __restrict__ g_state,
                    const float* __restrict__ g_radii,
                    const float* __restrict__ g_W1,
                    const float* __restrict__ g_b1,
                    const float* __restrict__ g_W2,
                    const float* __restrict__ g_b2,
                    const float* __restrict__ g_W3,
                    const float* __restrict__ g_b3,
                    float* __restrict__ g_out)
{
    __shared__ float4 own[NB];                 // this block's batch element (AoS: apply path only)
    __shared__ float2 sPos[NB];                // batch-0 positions (SoA)
    __shared__ float2 sVel[NB];                // batch-0 velocities (SoA)
    __shared__ float4 w2q[16*HID];             // w2q[k4*HID+o] = W2[o][4k4..4k4+3]
    __shared__ float w1s[2*HID];
    __shared__ float b1s[HID], b2s[HID], w3s[HID];
    __shared__ float4 h1q[2*16];
    __shared__ float h2buf[2*HID];
    __shared__ unsigned long long redK[NWARP];
    __shared__ float vmaxW[NWARP];
    __shared__ int nCandW[NWARP];
    __shared__ int candList[NWARP*SEGCAP];     // per-warp segments, packed (lo<<8)|hi
    __shared__ int sVmax2i;
    __shared__ float sMotion;
    __shared__ int sOverflow;
    __shared__ float sb3, srr;

    const int tid  = threadIdx.x;
    const int bidx = blockIdx.x;
    const int i0   = tid & (NB-1);
    const int half = tid >> 8;
    const int lane = tid & 31;
    const int warp = tid >> 5;

    // ---- setup ----
    if (tid < NB) {
        float4 v = reinterpret_cast<const float4*>(g_state)[bidx*NB + tid];
        own[tid] = v;
        float4 c = reinterpret_cast<const float4*>(g_state)[tid];
        sPos[tid] = make_float2(c.x, c.y);
        sVel[tid] = make_float2(c.z, c.w);
        reinterpret_cast<float4*>(g_out)[bidx*NB + tid] = v;
    }
    for (int q = tid; q < 16*HID; q += NTH) {
        int o = q & 63, k4 = q >> 6;
        const float* src = g_W2 + o*HID + k4*4;
        w2q[q] = make_float4(src[0], src[1], src[2], src[3]);
    }
    if (tid < 2*HID) w1s[tid] = g_W1[tid];
    if (tid < HID) { b1s[tid] = g_b1[tid]; b2s[tid] = g_b2[tid]; w3s[tid] = g_W3[tid]; }
    if (tid == 0) {
        sb3 = g_b3[0]; srr = g_radii[0];
        sMotion = 1e30f; sVmax2i = 0; sOverflow = 0;
    }
    __syncthreads();

    const float rr    = srr;
    const float two_r = rr + rr;
    const float cut   = two_r + 0.051f;        // exact narrow cutoff (gap>0.05 -> done)
    const float c2    = cut * cut;
    const float cute  = cut + MARGIN;          // broad-phase cutoff
    const float c2e   = cute * cute;
    const float b3v   = sb3;

    unsigned long long wkCache = ~0ull;        // cached min wall key of ball i0 (half==0)
    bool wkDirty = true;

    for (int s = 0; s < NSTEPS; ++s) {
        const float t_s = (float)s * 0.05f;
        const float t_e = t_s + 0.05f;
        float t_c = t_s;
        wkDirty = true;                        // step-end integration moved everything

        for (int ev = 0; ev < MAXEV; ++ev) {
            // ================= P0: detection =================
            const bool rebuild = (sOverflow != 0) || (sMotion >= MARGIN);
            const float2 mp = sPos[i0];
            const float2 mv = sVel[i0];
            unsigned long long key = ~0ull;

            if (rebuild) {
                // warp-max of speed^2 via REDUX (non-negative floats: uint-monotone)
                {
                    unsigned mu = __reduce_max_sync(0xFFFFFFFFu,
                                    __float_as_uint(mv.x*mv.x + mv.y*mv.y));
                    if (lane == 0) vmaxW[warp] = __uint_as_float(mu);
                }
                int cnt = 0;
                const int segBase = warp * SEGCAP;
                for (int d = 1 + half; d <= 127; d += 2) {
                    int j = (i0 + d) & (NB-1);
                    float2 pj = sPos[j];
                    float dx = pj.x - mp.x, dy = pj.y - mp.y;
                    float d2 = dx*dx + dy*dy;
                    bool push = (d2 <= c2e);
                    unsigned msk = __ballot_sync(0xFFFFFFFFu, push);
                    if (push) {
                        int lo = (i0 < j) ? i0 : j;
                        int hi = (i0 < j) ? j : i0;
                        int p = (lo << 8) | hi;
                        int slot = cnt + __popc(msk & ((1u << lane) - 1u));
                        if (slot < SEGCAP) candList[segBase + slot] = p;
                        if (d2 <= c2) {
                            float2 vj = sVel[j];
                            float dvx = vj.x - mv.x, dvy = vj.y - mv.y;
                            if (dvx*dx + dvy*dy < 0.0f)
                                fold_ball_key(key, p, d2, two_r);
                        }
                    }
                    cnt += __popc(msk);
                }
                if (half == 1 && i0 < 128) {               // d == 128 (warp-uniform)
                    int j = (i0 + 128) & (NB-1);
                    float2 pj = sPos[j];
                    float dx = pj.x - mp.x, dy = pj.y - mp.y;
                    float d2 = dx*dx + dy*dy;
                    bool push = (d2 <= c2e);
                    unsigned msk = __ballot_sync(0xFFFFFFFFu, push);
                    if (push) {
                        int p = (i0 << 8) | j;                 // i0 < j always here
                        int slot = cnt + __popc(msk & ((1u << lane) - 1u));
                        if (slot < SEGCAP) candList[segBase + slot] = p;
                        if (d2 <= c2) {
                            float2 vj = sVel[j];
                            float dvx = vj.x - mv.x, dvy = vj.y - mv.y;
                            if (dvx*dx + dvy*dy < 0.0f)
                                fold_ball_key(key, p, d2, two_r);
                        }
                    }
                    cnt += __popc(msk);
                }
                if (lane == 0) nCandW[warp] = cnt;
            } else {
                // event-time narrow scan: 2-way unrolled for LDS latency overlap
                const int seg  = tid & (NWARP-1);
                const int e0   = tid >> 4;                 // 0..31
                int n = nCandW[seg]; if (n > SEGCAP) n = SEGCAP;
                const int base = seg * SEGCAP;
                int e = e0;
                for (; e + 32 < n; e += 64) {
                    int p1 = candList[base + e];
                    int p2 = candList[base + e + 32];
                    int lo1 = p1 >> 8, hi1 = p1 & 255;
                    int lo2 = p2 >> 8, hi2 = p2 & 255;
                    float2 a1 = sPos[lo1], b1 = sPos[hi1];
                    float2 a2 = sPos[lo2], b2 = sPos[hi2];
                    float dx1 = b1.x - a1.x, dy1 = b1.y - a1.y;
                    float dx2 = b2.x - a2.x, dy2 = b2.y - a2.y;
                    float d21 = dx1*dx1 + dy1*dy1;
                    float d22 = dx2*dx2 + dy2*dy2;
                    if (d21 <= c2) {
                        float2 vl = sVel[lo1], vh = sVel[hi1];
                        float dvx = vh.x - vl.x, dvy = vh.y - vl.y;
                        if (dvx*dx1 + dvy*dy1 < 0.0f)
                            fold_ball_key(key, p1, d21, two_r);
                    }
                    if (d22 <= c2) {
                        float2 vl = sVel[lo2], vh = sVel[hi2];
                        float dvx = vh.x - vl.x, dvy = vh.y - vl.y;
                        if (dvx*dx2 + dvy*dy2 < 0.0f)
                            fold_ball_key(key, p2, d22, two_r);
                    }
                }
                if (e < n) {
                    int p = candList[base + e];
                    int lo = p >> 8, hi = p & 255;
                    float2 pl = sPos[lo], ph = sPos[hi];
                    float dx = ph.x - pl.x, dy = ph.y - pl.y;
                    float d2 = dx*dx + dy*dy;
                    if (d2 <= c2) {
                        float2 vl = sVel[lo], vh = sVel[hi];
                        float dvx = vh.x - vl.x, dvy = vh.y - vl.y;
                        if (dvx*dx + dvy*dy < 0.0f)
                            fold_ball_key(key, p, d2, two_r);
                    }
                }
            }

            // wall candidates (cached min-of-4 key; recompute only when ball i0 changed)
            if (half == 0) {
                if (wkDirty) {
                    unsigned long long wkmin = ~0ull;
                    float gs[4]; bool vs[4];
                    gs[0] = mp.x - rr;          vs[0] = mv.x < 0.0f;
                    gs[1] = 10.0f - mp.x - rr;  vs[1] = mv.x > 0.0f;
                    gs[2] = mp.y - rr;          vs[2] = mv.y < 0.0f;
                    gs[3] = 10.0f - mp.y - rr;  vs[3] = mv.y > 0.0f;
                    #pragma unroll
                    for (int w = 0; w < 4; ++w) {
                        if (vs[w]) {
                            unsigned u = __float_as_uint(gs[w]);
                            u = (u & 0x80000000u) ? ~u : (u | 0x80000000u);
                            unsigned long long k = ((unsigned long long)u << 32) |
                                                   0x80000000u | (unsigned)(i0*4 + w);
                            if (k < wkmin) wkmin = k;
                        }
                    }
                    wkCache = wkmin;
                    wkDirty = false;
                }
                if (wkCache < key) key = wkCache;
            }

            // warp REDUX min -> STS -> BAR -> block REDUX min over 16 slots
            key = warp_min_key(key);
            if (lane == 0) redK[warp] = key;
            __syncthreads();                              // ---- BAR A ----

            if (rebuild && tid == NTH-1) {
                float vm = vmaxW[0];
                #pragma unroll
                for (int w = 1; w < NWARP; ++w) vm = fmaxf(vm, vmaxW[w]);
                sVmax2i = __float_as_int(vm);
                int ov = 0;
                #pragma unroll
                for (int w = 0; w < NWARP; ++w) ov |= (nCandW[w] > SEGCAP);
                if (ov) sOverflow = 1;
                sMotion = 0.0f;
            }

            key = warp_min_key(redK[lane & (NWARP-1)]);

            const unsigned gHi = (unsigned)(key >> 32);
            if (gHi == 0xFFFFFFFFu) break;                 // no candidates -> done
            unsigned gu = (gHi & 0x80000000u) ? (gHi ^ 0x80000000u) : ~gHi;
            const float gap = __uint_as_float(gu);
            if (gap > 0.05f) break;                        // no_event -> done

            const unsigned lo32 = (unsigned)key;
            const bool is_ball = (lo32 < 0x80000000u);

            // redundant decode + flags on ALL threads
            int iA, iB = 0, wsel = 0;
            float app;
            if (is_ball) {
                iA = (int)((lo32 >> 8) & 255u);
                iB = (int)(lo32 & 255u);
                float2 pi = sPos[iA], pj = sPos[iB];
                float2 vi = sVel[iA], vj = sVel[iB];
                float nx = pj.x - pi.x, ny = pj.y - pi.y;
                float rL = rsqrtf(fmaxf(nx*nx + ny*ny, 1e-30f));
                app = -((vj.x - vi.x)*nx + (vj.y - vi.y)*ny) * rL;
            } else {
                unsigned idx = lo32 & 0x7FFFFFFFu;
                iA = (int)(idx >> 2);
                wsel = (int)(idx & 3u);
                float2 vi = sVel[iA];
                app = fabsf(fmaxf(vi.x, vi.y));
            }
            const float t_ev  = t_c + __fdividef(gap, fmaxf(app, 1e-6f));
            const bool case_a = (gap <= 0.0f);
            const bool case_b = (!case_a) && (app > 1e-6f) && (t_ev < t_e);
            if (!case_a && !case_b) break;                 // done
            const float dte = case_b ? ((t_ev > t_c + 1e-10f) ? (t_ev - t_c) : 0.0f) : 0.0f;
            if (case_b) t_c = t_ev;

            if (is_ball) {
                // warps 0-3: MLP; warps 4-11: integrate (skip iA,iB); thread 511: sMotion
                if (tid < 2*HID) {
                    int sel = tid >> 6, o = tid & (HID-1);
                    float4 si, sj;
                    if (sel) {
                        float2 p1 = sPos[iA], v1 = sVel[iA];
                        float2 p2 = sPos[iB], v2 = sVel[iB];
                        si = make_float4(p1.x, p1.y, v1.x, v1.y);
                        sj = make_float4(p2.x, p2.y, v2.x, v2.y);
                    } else {
                        si = own[iA]; sj = own[iB];
                    }
                    float six = fmaf(si.z, dte, si.x), siy = fmaf(si.w, dte, si.y);
                    float sjx = fmaf(sj.z, dte, sj.x), sjy = fmaf(sj.w, dte, sj.y);
                    float dx = sjx - six, dy = sjy - siy;
                    float d2h = dx*dx + dy*dy;
                    float ri = rsqrtf(fmaxf(d2h, 1e-30f));
                    float dist = fmaxf(d2h * ri, 1e-8f);
                    float nx = dx * ri, ny = dy * ri;
                    float ap = (sj.z - si.z)*nx + (sj.w - si.w)*ny;
                    float pre = dist*w1s[2*o] + ap*w1s[2*o+1] + b1s[o];
                    reinterpret_cast<float*>(h1q)[sel*HID + o] = silu_f(pre);
                    BAR_SYNC(3, 128);                     // h1 ready (warps 0-3)
                    const float4* H = &h1q[sel*16];
                    float a0 = 0.f, a1 = 0.f, a2 = 0.f, a3 = 0.f;
                    #pragma unroll 2
                    for (int k4 = 0; k4 < 16; k4 += 4) {
                        float4 w0 = w2q[(k4+0)*HID + o], hh0 = H[k4+0];
                        a0 = fmaf(w0.x,hh0.x,a0); a0 = fmaf(w0.y,hh0.y,a0);
                        a0 = fmaf(w0.z,hh0.z,a0); a0 = fmaf(w0.w,hh0.w,a0);
                        float4 w1v = w2q[(k4+1)*HID + o], hh1 = H[k4+1];
                        a1 = fmaf(w1v.x,hh1.x,a1); a1 = fmaf(w1v.y,hh1.y,a1);
                        a1 = fmaf(w1v.z,hh1.z,a1); a1 = fmaf(w1v.w,hh1.w,a1);
                        float4 w2v = w2q[(k4+2)*HID + o], hh2 = H[k4+2];
                        a2 = fmaf(w2v.x,hh2.x,a2); a2 = fmaf(w2v.y,hh2.y,a2);
                        a2 = fmaf(w2v.z,hh2.z,a2); a2 = fmaf(w2v.w,hh2.w,a2);
                        float4 w3v = w2q[(k4+3)*HID + o], hh3 = H[k4+3];
                        a3 = fmaf(w3v.x,hh3.x,a3); a3 = fmaf(w3v.y,hh3.y,a3);
                        a3 = fmaf(w3v.z,hh3.z,a3); a3 = fmaf(w3v.w,hh3.w,a3);
                    }
                    float acc = ((b2s[o] + a0) + a1) + (a2 + a3);
                    h2buf[sel*HID + o] = w3s[o] * silu_f(acc);
                    BAR_SYNC(3, 128);                     // h2 ready (warps 0-3)
                    if (warp == 0 || warp == 2) {
                        int sl = warp >> 1;
                        float v = h2buf[sl*HID + lane] + h2buf[sl*HID + 32 + lane];
                        #pragma unroll
                        for (int off = 16; off > 0; off >>= 1)
                            v += __shfl_down_sync(0xFFFFFFFFu, v, off);
                        if (lane == 0) {
                            float impv = v + b3v;
                            float4 ti, tj;
                            if (sl) {
                                float2 p1 = sPos[iA], v1 = sVel[iA];
                                float2 p2 = sPos[iB], v2 = sVel[iB];
                                ti = make_float4(p1.x, p1.y, v1.x, v1.y);
                                tj = make_float4(p2.x, p2.y, v2.x, v2.y);
                            } else {
                                ti = own[iA]; tj = own[iB];
                            }
                            float tix = fmaf(ti.z, dte, ti.x), tiy = fmaf(ti.w, dte, ti.y);
                            float tjx = fmaf(tj.z, dte, tj.x), tjy = fmaf(tj.w, dte, tj.y);
                            float ddx = tjx - tix, ddy = tjy - tiy;
                            float dd2 = ddx*ddx + ddy*ddy;
                            float rst = rsqrtf(fmaxf(dd2, 1e-30f));
                            // match h1's clamped-dist normalization exactly
                            float dstc = fmaxf(dd2 * rst, 1e-8f);
                            float rdc = __fdividef(1.0f, dstc);
                            float nnx = ddx*rdc, nny = ddy*rdc;
                            float niz = ti.z + impv*nnx, niw = ti.w + impv*nny;
                            float njz = tj.z - impv*nnx, njw = tj.w - impv*nny;
                            if (sl) {
                                sPos[iA] = make_float2(tix, tiy);
                                sPos[iB] = make_float2(tjx, tjy);
                                sVel[iA] = make_float2(niz, niw);
                                sVel[iB] = make_float2(njz, njw);
                                float sp = fmaxf(niz*niz + niw*niw, njz*njz + njw*njw);
                                atomicMax(&sVmax2i, __float_as_int(sp));
                            } else {
                                own[iA] = make_float4(tix, tiy, niz, niw);
                                own[iB] = make_float4(tjx, tjy, njz, njw);
                            }
                        }
                    }
                } else if (tid < 384) {
                    int b = tid - 128;
                    if (dte != 0.0f && b != iA && b != iB) {
                        float4 v = own[b];
                        v.x = fmaf(v.z, dte, v.x); v.y = fmaf(v.w, dte, v.y);
                        own[b] = v;
                        float2 p = sPos[b], vv = sVel[b];
                        sPos[b] = make_float2(fmaf(vv.x, dte, p.x), fmaf(vv.y, dte, p.y));
                    }
                } else if (tid == NTH-1) {
                    sMotion += 2.0f * sqrtf(__int_as_float(sVmax2i)) * dte;
                }
                __syncthreads();                          // ---- BAR E ----
            } else {
                // wall: compute result + integrate (b != iA) pre-barrier; write iA after
                float4 res; float pen = 0.0f;
                if (tid < 2) {
                    float4 si;
                    if (tid) {
                        float2 p1 = sPos[iA], v1 = sVel[iA];
                        si = make_float4(p1.x, p1.y, v1.x, v1.y);
                    } else {
                        si = own[iA];
                    }
                    float six = fmaf(si.z, dte, si.x), siy = fmaf(si.w, dte, si.y);
                    float wnx = 0.0f, wny = 0.0f, wp = 0.0f;
                    if      (wsel == 0) { wnx =  1.0f; }
                    else if (wsel == 1) { wnx = -1.0f; wp = -10.0f; }
                    else if (wsel == 2) { wny =  1.0f; }
                    else                { wny = -1.0f; wp = -10.0f; }
                    float vn  = si.z*wnx + si.w*wny;
                    float nvx = si.z - 2.0f*vn*wnx;
                    float nvy = si.w - 2.0f*vn*wny;
                    float pn  = six*wnx + siy*wny;
                    pen = fmaxf(wp + rr - pn, 0.0f);
                    res = make_float4(six + pen*wnx, siy + pen*wny, nvx, nvy);
                } else if (tid >= 128 && tid < 384) {
                    int b = tid - 128;
                    if (dte != 0.0f && b != iA) {
                        float4 v = own[b];
                        v.x = fmaf(v.z, dte, v.x); v.y = fmaf(v.w, dte, v.y);
                        own[b] = v;
                        float2 p = sPos[b], vv = sVel[b];
                        sPos[b] = make_float2(fmaf(vv.x, dte, p.x), fmaf(vv.y, dte, p.y));
                    }
                }
                __syncthreads();                          // ---- BAR W1 ----
                if (tid < 2) {
                    if (tid) {
                        sPos[iA] = make_float2(res.x, res.y);
                        sVel[iA] = make_float2(res.z, res.w);
                        sMotion += 2.0f * sqrtf(__int_as_float(sVmax2i)) * dte + pen;
                    } else {
                        own[iA] = res;
                    }
                }
                __syncthreads();                          // ---- BAR W2 ----
            }

            // wall-key cache invalidation (ball i0's pos/vel changed?)
            if (half == 0) {
                if (dte != 0.0f || i0 == iA || (is_ball && i0 == iB)) wkDirty = true;
            }
        }  // events

        // ---- step end ----
        __syncthreads();                                  // orders break-path reads vs writes
        const float dte2 = (t_e > t_c + 1e-10f) ? (t_e - t_c) : 0.0f;
        if (tid < NB) {
            float4 v = own[tid];
            v.x = fmaf(v.z, dte2, v.x); v.y = fmaf(v.w, dte2, v.y);
            own[tid] = v;
            float2 p = sPos[tid], vv = sVel[tid];
            sPos[tid] = make_float2(fmaf(vv.x, dte2, p.x), fmaf(vv.y, dte2, p.y));
            reinterpret_cast<float4*>(g_out)[((long)(s+1)*BATCHN + bidx)*NB + tid] = v;
        }
        if (tid == 0)
            sMotion += 2.0f * sqrtf(__int_as_float(sVmax2i)) * dte2;
        __syncthreads();
    }
}

extern "C" void kernel_launch(void* const* d_in, const int* in_sizes, int n_in,
                              void* d_out, int out_size) {
    (void)in_sizes; (void)n_in; (void)out_size;
    hybrid_rollout<<<BATCHN, NTH>>>(
        (const float*)d_in[0], (const float*)d_in[1],
        (const float*)d_in[2], (const float*)d_in[3],
        (const float*)d_in[4], (const float*)d_in[5],
        (const float*)d_in[6], (const float*)d_in[7],
        (float*)d_out);
}

// round 15
// speedup vs baseline: 1.3947x; 1.0240x over previous
#include <cuda_runtime.h>
#include <cuda_bf16.h>
#include <math.h>

#define NB 256
#define BATCHN 128
#define NSTEPS 100
#define MAXEV 5
#define HID 64
#define NTH 512
#define NWARP (NTH/32)
#define SEGCAP 388
#define MARGIN 1.0f

#define BAR_SYNC(id,cnt)   asm volatile("bar.sync %0, %1;"   :: "r"(id), "r"(cnt) : "memory")

__device__ __forceinline__ float silu_f(float x) {
    return __fdividef(x, 1.0f + __expf(-x));
}

// lexicographic 64-bit min across full warp via 2x REDUX.MIN.u32
__device__ __forceinline__ unsigned long long warp_min_key(unsigned long long key) {
    unsigned hi = (unsigned)(key >> 32), lo = (unsigned)key;
    unsigned mh = __reduce_min_sync(0xFFFFFFFFu, hi);
    unsigned cl = (hi == mh) ? lo : 0xFFFFFFFFu;
    unsigned ml = __reduce_min_sync(0xFFFFFFFFu, cl);
    return ((unsigned long long)mh << 32) | ml;
}

__device__ __forceinline__ void fold_ball_key(unsigned long long& key, int p, float d2, float two_r) {
    float gap = sqrtf(d2) - two_r;
    unsigned gu = __float_as_uint(gap);
    gu = (gu & 0x80000000u) ? ~gu : (gu | 0x80000000u);   // monotone float->uint
    unsigned long long k = ((unsigned long long)gu << 32) | (unsigned)p;
    if (k < key) key = k;
}

__global__ __launch_bounds__(NTH, 1)
void hybrid_rollout(const float* __restrict__ g_state,
                    const float* __restrict__ g_radii,
                    const float* __restrict__ g_W1,
                    const float* __restrict__ g_b1,
                    const float* __restrict__ g_W2,
                    const float* __restrict__ g_b2,
                    const float* __restrict__ g_W3,
                    const float* __restrict__ g_b3,
                    float* __restrict__ g_out)
{
    __shared__ float4 own[NB];                 // this block's batch element (AoS: apply path only)
    __shared__ float2 sPos[NB];                // batch-0 positions (SoA)
    __shared__ float2 sVel[NB];                // batch-0 velocities (SoA)
    __shared__ float4 w2q[16*HID];             // w2q[k4*HID+o] = W2[o][4k4..4k4+3]
    __shared__ float w1s[2*HID];
    __shared__ float b1s[HID], b2s[HID], w3s[HID];
    __shared__ float4 h1q[2*16];
    __shared__ float h2buf[2*HID];
    __shared__ unsigned long long redK[NWARP];
    __shared__ float vmaxW[NWARP];
    __shared__ int nCandW[NWARP];
    __shared__ int candList[NWARP*SEGCAP];     // per-warp segments (16B aligned), (lo<<8)|hi
    __shared__ int sVmax2i;
    __shared__ float sMotion;
    __shared__ int sOverflow;
    __shared__ float sb3, srr;

    const int tid  = threadIdx.x;
    const int bidx = blockIdx.x;
    const int i0   = tid & (NB-1);
    const int half = tid >> 8;
    const int lane = tid & 31;
    const int warp = tid >> 5;

    // ---- setup ----
    if (tid < NB) {
        float4 v = reinterpret_cast<const float4*>(g_state)[bidx*NB + tid];
        own[tid] = v;
        float4 c = reinterpret_cast<const float4*>(g_state)[tid];
        sPos[tid] = make_float2(c.x, c.y);
        sVel[tid] = make_float2(c.z, c.w);
        reinterpret_cast<float4*>(g_out)[bidx*NB + tid] = v;
    }
    for (int q = tid; q < 16*HID; q += NTH) {
        int o = q & 63, k4 = q >> 6;
        const float* src = g_W2 + o*HID + k4*4;
        w2q[q] = make_float4(src[0], src[1], src[2], src[3]);
    }
    if (tid < 2*HID) w1s[tid] = g_W1[tid];
    if (tid < HID) { b1s[tid] = g_b1[tid]; b2s[tid] = g_b2[tid]; w3s[tid] = g_W3[tid]; }
    if (tid == 0) {
        sb3 = g_b3[0]; srr = g_radii[0];
        sMotion = 1e30f; sVmax2i = 0; sOverflow = 0;
    }
    __syncthreads();

    const float rr    = srr;
    const float two_r = rr + rr;
    const float cut   = two_r + 0.051f;        // exact narrow cutoff (gap>0.05 -> done)
    const float c2    = cut * cut;
    const float cute  = cut + MARGIN;          // broad-phase cutoff
    const float c2e   = cute * cute;
    const float b3v   = sb3;

    unsigned long long wkCache = ~0ull;        // cached min wall key of ball i0 (half==0)
    bool wkDirty = true;

    for (int s = 0; s < NSTEPS; ++s) {
        const float t_s = (float)s * 0.05f;
        const float t_e = t_s + 0.05f;
        float t_c = t_s;
        wkDirty = true;                        // step-end integration moved everything

        for (int ev = 0; ev < MAXEV; ++ev) {
            // ================= P0: detection =================
            const bool rebuild = (sOverflow != 0) || (sMotion >= MARGIN);
            const float2 mp = sPos[i0];
            const float2 mv = sVel[i0];
            unsigned long long key = ~0ull;

            if (rebuild) {
                // warp-max of speed^2 via REDUX (non-negative floats: uint-monotone)
                {
                    unsigned mu = __reduce_max_sync(0xFFFFFFFFu,
                                    __float_as_uint(mv.x*mv.x + mv.y*mv.y));
                    if (lane == 0) vmaxW[warp] = __uint_as_float(mu);
                }
                int cnt = 0;
                const int segBase = warp * SEGCAP;
                for (int d = 1 + half; d <= 127; d += 2) {
                    int j = (i0 + d) & (NB-1);
                    float2 pj = sPos[j];
                    float dx = pj.x - mp.x, dy = pj.y - mp.y;
                    float d2 = dx*dx + dy*dy;
                    bool push = (d2 <= c2e);
                    unsigned msk = __ballot_sync(0xFFFFFFFFu, push);
                    if (push) {
                        int lo = (i0 < j) ? i0 : j;
                        int hi = (i0 < j) ? j : i0;
                        int p = (lo << 8) | hi;
                        int slot = cnt + __popc(msk & ((1u << lane) - 1u));
                        if (slot < SEGCAP) candList[segBase + slot] = p;
                        if (d2 <= c2) {
                            float2 vj = sVel[j];
                            float dvx = vj.x - mv.x, dvy = vj.y - mv.y;
                            if (dvx*dx + dvy*dy < 0.0f)
                                fold_ball_key(key, p, d2, two_r);
                        }
                    }
                    cnt += __popc(msk);
                }
                if (half == 1 && i0 < 128) {               // d == 128 (warp-uniform)
                    int j = (i0 + 128) & (NB-1);
                    float2 pj = sPos[j];
                    float dx = pj.x - mp.x, dy = pj.y - mp.y;
                    float d2 = dx*dx + dy*dy;
                    bool push = (d2 <= c2e);
                    unsigned msk = __ballot_sync(0xFFFFFFFFu, push);
                    if (push) {
                        int p = (i0 << 8) | j;                 // i0 < j always here
                        int slot = cnt + __popc(msk & ((1u << lane) - 1u));
                        if (slot < SEGCAP) candList[segBase + slot] = p;
                        if (d2 <= c2) {
                            float2 vj = sVel[j];
                            float dvx = vj.x - mv.x, dvy = vj.y - mv.y;
                            if (dvx*dx + dvy*dy < 0.0f)
                                fold_ball_key(key, p, d2, two_r);
                        }
                    }
                    cnt += __popc(msk);
                }
                // pad segment to multiple of 4 with sentinel pair (0,0): key-inert
                if (lane < 4) {
                    int k = cnt + lane;
                    int kend = (cnt + 3) & ~3;
                    if (k < kend && k < SEGCAP) candList[segBase + k] = 0;
                }
                if (lane == 0) nCandW[warp] = cnt;
            } else {
                // event-time narrow scan: warp scans its OWN segment, int4 loads,
                // uniform trip count (nCandW[warp] is warp-uniform), sentinel-padded
                const int base = warp * SEGCAP;
                int n = nCandW[warp]; if (n > SEGCAP) n = SEGCAP;
                const int n4 = (n + 3) & ~3;
                for (int e4 = lane * 4; e4 < n4; e4 += 128) {
                    int4 pk = *reinterpret_cast<const int4*>(&candList[base + e4]);
                    #pragma unroll
                    for (int i = 0; i < 4; ++i) {
                        int p = (&pk.x)[i];
                        int lo = p >> 8, hi = p & 255;
                        float2 pl = sPos[lo], ph = sPos[hi];
                        float dx = ph.x - pl.x, dy = ph.y - pl.y;
                        float d2 = dx*dx + dy*dy;
                        if (d2 <= c2) {
                            float2 vl = sVel[lo], vh = sVel[hi];
                            float dvx = vh.x - vl.x, dvy = vh.y - vl.y;
                            if (dvx*dx + dvy*dy < 0.0f)
                                fold_ball_key(key, p, d2, two_r);
                        }
                    }
                }
            }

            // wall candidates (cached min-of-4 key; recompute only when ball i0 changed)
            if (half == 0) {
                if (wkDirty) {
                    unsigned long long wkmin = ~0ull;
                    float gs[4]; bool vs[4];
                    gs[0] = mp.x - rr;          vs[0] = mv.x < 0.0f;
                    gs[1] = 10.0f - mp.x - rr;  vs[1] = mv.x > 0.0f;
                    gs[2] = mp.y - rr;          vs[2] = mv.y < 0.0f;
                    gs[3] = 10.0f - mp.y - rr;  vs[3] = mv.y > 0.0f;
                    #pragma unroll
                    for (int w = 0; w < 4; ++w) {
                        if (vs[w]) {
                            unsigned u = __float_as_uint(gs[w]);
                            u = (u & 0x80000000u) ? ~u : (u | 0x80000000u);
                            unsigned long long k = ((unsigned long long)u << 32) |
                                                   0x80000000u | (unsigned)(i0*4 + w);
                            if (k < wkmin) wkmin = k;
                        }
                    }
                    wkCache = wkmin;
                    wkDirty = false;
                }
                if (wkCache < key) key = wkCache;
            }

            // warp REDUX min -> STS -> BAR -> block REDUX min over 16 slots
            key = warp_min_key(key);
            if (lane == 0) redK[warp] = key;
            __syncthreads();                              // ---- BAR A ----

            if (rebuild && tid == NTH-1) {
                float vm = vmaxW[0];
                #pragma unroll
                for (int w = 1; w < NWARP; ++w) vm = fmaxf(vm, vmaxW[w]);
                sVmax2i = __float_as_int(vm);
                int ov = 0;
                #pragma unroll
                for (int w = 0; w < NWARP; ++w) ov |= (nCandW[w] > SEGCAP - 3);
                if (ov) sOverflow = 1;
                sMotion = 0.0f;
            }

            key = warp_min_key(redK[lane & (NWARP-1)]);

            const unsigned gHi = (unsigned)(key >> 32);
            if (gHi == 0xFFFFFFFFu) break;                 // no candidates -> done
            unsigned gu = (gHi & 0x80000000u) ? (gHi ^ 0x80000000u) : ~gHi;
            const float gap = __uint_as_float(gu);
            if (gap > 0.05f) break;                        // no_event -> done

            const unsigned lo32 = (unsigned)key;
            const bool is_ball = (lo32 < 0x80000000u);

            // redundant decode + flags on ALL threads
            int iA, iB = 0, wsel = 0;
            float app;
            if (is_ball) {
                iA = (int)((lo32 >> 8) & 255u);
                iB = (int)(lo32 & 255u);
                float2 pi = sPos[iA], pj = sPos[iB];
                float2 vi = sVel[iA], vj = sVel[iB];
                float nx = pj.x - pi.x, ny = pj.y - pi.y;
                float rL = rsqrtf(fmaxf(nx*nx + ny*ny, 1e-30f));
                app = -((vj.x - vi.x)*nx + (vj.y - vi.y)*ny) * rL;
            } else {
                unsigned idx = lo32 & 0x7FFFFFFFu;
                iA = (int)(idx >> 2);
                wsel = (int)(idx & 3u);
                float2 vi = sVel[iA];
                app = fabsf(fmaxf(vi.x, vi.y));
            }
            const float t_ev  = t_c + __fdividef(gap, fmaxf(app, 1e-6f));
            const bool case_a = (gap <= 0.0f);
            const bool case_b = (!case_a) && (app > 1e-6f) && (t_ev < t_e);
            if (!case_a && !case_b) break;                 // done
            const float dte = case_b ? ((t_ev > t_c + 1e-10f) ? (t_ev - t_c) : 0.0f) : 0.0f;
            if (case_b) t_c = t_ev;

            if (is_ball) {
                // warps 0-3: MLP; warps 4-11: integrate (skip iA,iB); thread 511: sMotion
                if (tid < 2*HID) {
                    int sel = tid >> 6, o = tid & (HID-1);
                    float4 si, sj;
                    if (sel) {
                        float2 p1 = sPos[iA], v1 = sVel[iA];
                        float2 p2 = sPos[iB], v2 = sVel[iB];
                        si = make_float4(p1.x, p1.y, v1.x, v1.y);
                        sj = make_float4(p2.x, p2.y, v2.x, v2.y);
                    } else {
                        si = own[iA]; sj = own[iB];
                    }
                    float six = fmaf(si.z, dte, si.x), siy = fmaf(si.w, dte, si.y);
                    float sjx = fmaf(sj.z, dte, sj.x), sjy = fmaf(sj.w, dte, sj.y);
                    float dx = sjx - six, dy = sjy - siy;
                    float d2h = dx*dx + dy*dy;
                    float ri = rsqrtf(fmaxf(d2h, 1e-30f));
                    float dist = fmaxf(d2h * ri, 1e-8f);
                    float nx = dx * ri, ny = dy * ri;
                    float ap = (sj.z - si.z)*nx + (sj.w - si.w)*ny;
                    float pre = dist*w1s[2*o] + ap*w1s[2*o+1] + b1s[o];
                    reinterpret_cast<float*>(h1q)[sel*HID + o] = silu_f(pre);
                    BAR_SYNC(3, 128);                     // h1 ready (warps 0-3)
                    const float4* H = &h1q[sel*16];
                    float a0 = 0.f, a1 = 0.f, a2 = 0.f, a3 = 0.f;
                    #pragma unroll 2
                    for (int k4 = 0; k4 < 16; k4 += 4) {
                        float4 w0 = w2q[(k4+0)*HID + o], hh0 = H[k4+0];
                        a0 = fmaf(w0.x,hh0.x,a0); a0 = fmaf(w0.y,hh0.y,a0);
                        a0 = fmaf(w0.z,hh0.z,a0); a0 = fmaf(w0.w,hh0.w,a0);
                        float4 w1v = w2q[(k4+1)*HID + o], hh1 = H[k4+1];
                        a1 = fmaf(w1v.x,hh1.x,a1); a1 = fmaf(w1v.y,hh1.y,a1);
                        a1 = fmaf(w1v.z,hh1.z,a1); a1 = fmaf(w1v.w,hh1.w,a1);
                        float4 w2v = w2q[(k4+2)*HID + o], hh2 = H[k4+2];
                        a2 = fmaf(w2v.x,hh2.x,a2); a2 = fmaf(w2v.y,hh2.y,a2);
                        a2 = fmaf(w2v.z,hh2.z,a2); a2 = fmaf(w2v.w,hh2.w,a2);
                        float4 w3v = w2q[(k4+3)*HID + o], hh3 = H[k4+3];
                        a3 = fmaf(w3v.x,hh3.x,a3); a3 = fmaf(w3v.y,hh3.y,a3);
                        a3 = fmaf(w3v.z,hh3.z,a3); a3 = fmaf(w3v.w,hh3.w,a3);
                    }
                    float acc = ((b2s[o] + a0) + a1) + (a2 + a3);
                    h2buf[sel*HID + o] = w3s[o] * silu_f(acc);
                    BAR_SYNC(3, 128);                     // h2 ready (warps 0-3)
                    if (warp == 0 || warp == 2) {
                        int sl = warp >> 1;
                        float v = h2buf[sl*HID + lane] + h2buf[sl*HID + 32 + lane];
                        #pragma unroll
                        for (int off = 16; off > 0; off >>= 1)
                            v += __shfl_down_sync(0xFFFFFFFFu, v, off);
                        if (lane == 0) {
                            float impv = v + b3v;
                            float4 ti, tj;
                            if (sl) {
                                float2 p1 = sPos[iA], v1 = sVel[iA];
                                float2 p2 = sPos[iB], v2 = sVel[iB];
                                ti = make_float4(p1.x, p1.y, v1.x, v1.y);
                                tj = make_float4(p2.x, p2.y, v2.x, v2.y);
                            } else {
                                ti = own[iA]; tj = own[iB];
                            }
                            float tix = fmaf(ti.z, dte, ti.x), tiy = fmaf(ti.w, dte, ti.y);
                            float tjx = fmaf(tj.z, dte, tj.x), tjy = fmaf(tj.w, dte, tj.y);
                            float ddx = tjx - tix, ddy = tjy - tiy;
                            float dd2 = ddx*ddx + ddy*ddy;
                            float rst = rsqrtf(fmaxf(dd2, 1e-30f));
                            // match h1's clamped-dist normalization exactly
                            float dstc = fmaxf(dd2 * rst, 1e-8f);
                            float rdc = __fdividef(1.0f, dstc);
                            float nnx = ddx*rdc, nny = ddy*rdc;
                            float niz = ti.z + impv*nnx, niw = ti.w + impv*nny;
                            float njz = tj.z - impv*nnx, njw = tj.w - impv*nny;
                            if (sl) {
                                sPos[iA] = make_float2(tix, tiy);
                                sPos[iB] = make_float2(tjx, tjy);
                                sVel[iA] = make_float2(niz, niw);
                                sVel[iB] = make_float2(njz, njw);
                                float sp = fmaxf(niz*niz + niw*niw, njz*njz + njw*njw);
                                atomicMax(&sVmax2i, __float_as_int(sp));
                            } else {
                                own[iA] = make_float4(tix, tiy, niz, niw);
                                own[iB] = make_float4(tjx, tjy, njz, njw);
                            }
                        }
                    }
                } else if (tid < 384) {
                    int b = tid - 128;
                    if (dte != 0.0f && b != iA && b != iB) {
                        float4 v = own[b];
                        v.x = fmaf(v.z, dte, v.x); v.y = fmaf(v.w, dte, v.y);
                        own[b] = v;
                        float2 p = sPos[b], vv = sVel[b];
                        sPos[b] = make_float2(fmaf(vv.x, dte, p.x), fmaf(vv.y, dte, p.y));
                    }
                } else if (tid == NTH-1) {
                    sMotion += 2.0f * sqrtf(__int_as_float(sVmax2i)) * dte;
                }
                __syncthreads();                          // ---- BAR E ----
            } else {
                // wall: compute result + integrate (b != iA) pre-barrier; write iA after
                float4 res; float pen = 0.0f;
                if (tid < 2) {
                    float4 si;
                    if (tid) {
                        float2 p1 = sPos[iA], v1 = sVel[iA];
                        si = make_float4(p1.x, p1.y, v1.x, v1.y);
                    } else {
                        si = own[iA];
                    }
                    float six = fmaf(si.z, dte, si.x), siy = fmaf(si.w, dte, si.y);
                    float wnx = 0.0f, wny = 0.0f, wp = 0.0f;
                    if      (wsel == 0) { wnx =  1.0f; }
                    else if (wsel == 1) { wnx = -1.0f; wp = -10.0f; }
                    else if (wsel == 2) { wny =  1.0f; }
                    else                { wny = -1.0f; wp = -10.0f; }
                    float vn  = si.z*wnx + si.w*wny;
                    float nvx = si.z - 2.0f*vn*wnx;
                    float nvy = si.w - 2.0f*vn*wny;
                    float pn  = six*wnx + siy*wny;
                    pen = fmaxf(wp + rr - pn, 0.0f);
                    res = make_float4(six + pen*wnx, siy + pen*wny, nvx, nvy);
                } else if (tid >= 128 && tid < 384) {
                    int b = tid - 128;
                    if (dte != 0.0f && b != iA) {
                        float4 v = own[b];
                        v.x = fmaf(v.z, dte, v.x); v.y = fmaf(v.w, dte, v.y);
                        own[b] = v;
                        float2 p = sPos[b], vv = sVel[b];
                        sPos[b] = make_float2(fmaf(vv.x, dte, p.x), fmaf(vv.y, dte, p.y));
                    }
                }
                __syncthreads();                          // ---- BAR W1 ----
                if (tid < 2) {
                    if (tid) {
                        sPos[iA] = make_float2(res.x, res.y);
                        sVel[iA] = make_float2(res.z, res.w);
                        sMotion += 2.0f * sqrtf(__int_as_float(sVmax2i)) * dte + pen;
                    } else {
                        own[iA] = res;
                    }
                }
                __syncthreads();                          // ---- BAR W2 ----
            }

            // wall-key cache invalidation (ball i0's pos/vel changed?)
            if (half == 0) {
                if (dte != 0.0f || i0 == iA || (is_ball && i0 == iB)) wkDirty = true;
            }
        }  // events

        // ---- step end ----
        __syncthreads();                                  // orders break-path reads vs writes
        const float dte2 = (t_e > t_c + 1e-10f) ? (t_e - t_c) : 0.0f;
        if (tid < NB) {
            float4 v = own[tid];
            v.x = fmaf(v.z, dte2, v.x); v.y = fmaf(v.w, dte2, v.y);
            own[tid] = v;
            float2 p = sPos[tid], vv = sVel[tid];
            sPos[tid] = make_float2(fmaf(vv.x, dte2, p.x), fmaf(vv.y, dte2, p.y));
            reinterpret_cast<float4*>(g_out)[((long)(s+1)*BATCHN + bidx)*NB + tid] = v;
        }
        if (tid == 0)
            sMotion += 2.0f * sqrtf(__int_as_float(sVmax2i)) * dte2;
        __syncthreads();
    }
}

extern "C" void kernel_launch(void* const* d_in, const int* in_sizes, int n_in,
                              void* d_out, int out_size) {
    (void)in_sizes; (void)n_in; (void)out_size;
    hybrid_rollout<<<BATCHN, NTH>>>(
        (const float*)d_in[0], (const float*)d_in[1],
        (const float*)d_in[2], (const float*)d_in[3],
        (const float*)d_in[4], (const float*)d_in[5],
        (const float*)d_in[6], (const float*)d_in[7],
        (float*)d_out);
}